// round 1
// baseline (speedup 1.0000x reference)
#include <cuda_runtime.h>
#include <cuda_bf16.h>
#include <math.h>

// Problem constants
#define BB   128
#define NN   197
#define CC   768
#define HH   12
#define HD   64
#define OUTC 32
#define CHH  14
#define CHD  14
#define CNN  196
#define MLPH 3072
#define CMLPH 128
#define MROWS (BB*NN)          // 25216
#define CMROWS (BB*OUTC)       // 4096

// ---------------- scratch (device globals; no runtime allocation) ----------------
__device__ float g_ln  [MROWS*CC];          // LN1/LN2 output
__device__ float g_qkv [MROWS*3*CC];        // qkv
__device__ float g_attn[(size_t)BB*HH*NN*NN]; // attention probs
__device__ float g_o   [MROWS*CC];          // attn output
__device__ float g_x   [MROWS*CC];          // running x (768ch)
__device__ float g_mlp [(size_t)MROWS*MLPH];// mlp hidden
__device__ float g_x32 [MROWS*OUTC];        // x after channel squeeze
__device__ float g_ln32[MROWS*OUTC];        // LN3/LN4 output
__device__ float g_t   [BB*OUTC*CNN];       // transposed tokens
__device__ float g_cqkv[BB*OUTC*3*CNN];     // channel qkv
__device__ float g_co  [BB*OUTC*CNN];       // channel attn out
__device__ float g_co2 [BB*OUTC*CNN];       // channel proj out
__device__ float g_cmlp[MROWS*CMLPH];       // channel mlp hidden

__device__ __forceinline__ float gelu_f(float x) {
    return 0.5f * x * (1.0f + erff(x * 0.70710678118654752440f));
}

// ---------------- LayerNorm D=768, one block(256) per row ----------------
__global__ void ln768_kernel(const float* __restrict__ x, const float* __restrict__ g,
                             const float* __restrict__ b, float* __restrict__ out) {
    int row = blockIdx.x;
    const float* p = x + (size_t)row * CC;
    float* o = out + (size_t)row * CC;
    int tid = threadIdx.x;
    float v0 = p[tid], v1 = p[tid + 256], v2 = p[tid + 512];
    float s = v0 + v1 + v2;
    float sq = v0 * v0 + v1 * v1 + v2 * v2;
    __shared__ float rs[256], rq[256];
    rs[tid] = s; rq[tid] = sq; __syncthreads();
    for (int st = 128; st > 0; st >>= 1) {
        if (tid < st) { rs[tid] += rs[tid + st]; rq[tid] += rq[tid + st]; }
        __syncthreads();
    }
    float mean = rs[0] * (1.0f / CC);
    float var  = rq[0] * (1.0f / CC) - mean * mean;
    float inv = rsqrtf(var + 1e-5f);
    o[tid]       = (v0 - mean) * inv * g[tid]       + b[tid];
    o[tid + 256] = (v1 - mean) * inv * g[tid + 256] + b[tid + 256];
    o[tid + 512] = (v2 - mean) * inv * g[tid + 512] + b[tid + 512];
}

// ---------------- LayerNorm D=32, one warp per row, 8 rows/block ----------------
__global__ void ln32_kernel(const float* __restrict__ x, const float* __restrict__ g,
                            const float* __restrict__ b, float* __restrict__ out) {
    int row = blockIdx.x * 8 + threadIdx.x / 32;
    int lane = threadIdx.x & 31;
    float v = x[(size_t)row * OUTC + lane];
    float s = v, sq = v * v;
    #pragma unroll
    for (int o = 16; o > 0; o >>= 1) {
        s  += __shfl_xor_sync(0xffffffff, s, o);
        sq += __shfl_xor_sync(0xffffffff, sq, o);
    }
    float mean = s * (1.0f / OUTC);
    float var  = sq * (1.0f / OUTC) - mean * mean;
    float inv = rsqrtf(var + 1e-5f);
    out[(size_t)row * OUTC + lane] = (v - mean) * inv * g[lane] + b[lane];
}

// ---------------- Generic NT GEMM: C[M,N] = epi(A[M,K] * B[N,K]^T + bias) (+res) ----
// M must be a multiple of BM. N,K arbitrary (K%4==0 required for float4 loads).
template<int BM, int BN, int BK, int TM, int TN, bool GELU, bool RES>
__global__ void gemm_nt(const float* __restrict__ A, const float* __restrict__ Bw,
                        const float* __restrict__ bias, const float* __restrict__ res,
                        float* __restrict__ C, int M, int N, int K) {
    constexpr int THREADS = (BM / TM) * (BN / TN);
    __shared__ float As[BK][BM];
    __shared__ float Bs[BK][BN];
    int tid = threadIdx.x;
    int bm = blockIdx.y * BM, bn = blockIdx.x * BN;
    int tx = tid % (BN / TN), ty = tid / (BN / TN);
    float acc[TM][TN];
    #pragma unroll
    for (int i = 0; i < TM; i++)
        #pragma unroll
        for (int j = 0; j < TN; j++) acc[i][j] = 0.0f;

    constexpr int A4 = BM * BK / 4;
    constexpr int B4 = BN * BK / 4;

    for (int k0 = 0; k0 < K; k0 += BK) {
        #pragma unroll
        for (int i = tid; i < A4; i += THREADS) {
            int row = i / (BK / 4);
            int kk  = (i % (BK / 4)) * 4;
            float4 v = make_float4(0.f, 0.f, 0.f, 0.f);
            if (k0 + kk < K) v = *(const float4*)(A + (size_t)(bm + row) * K + k0 + kk);
            As[kk + 0][row] = v.x; As[kk + 1][row] = v.y;
            As[kk + 2][row] = v.z; As[kk + 3][row] = v.w;
        }
        #pragma unroll
        for (int i = tid; i < B4; i += THREADS) {
            int row = i / (BK / 4);
            int kk  = (i % (BK / 4)) * 4;
            float4 v = make_float4(0.f, 0.f, 0.f, 0.f);
            if (bn + row < N && k0 + kk < K)
                v = *(const float4*)(Bw + (size_t)(bn + row) * K + k0 + kk);
            Bs[kk + 0][row] = v.x; Bs[kk + 1][row] = v.y;
            Bs[kk + 2][row] = v.z; Bs[kk + 3][row] = v.w;
        }
        __syncthreads();
        #pragma unroll
        for (int kk = 0; kk < BK; kk++) {
            float a[TM], bv[TN];
            #pragma unroll
            for (int i = 0; i < TM; i++) a[i] = As[kk][ty * TM + i];
            #pragma unroll
            for (int j = 0; j < TN; j++) bv[j] = Bs[kk][tx * TN + j];
            #pragma unroll
            for (int i = 0; i < TM; i++)
                #pragma unroll
                for (int j = 0; j < TN; j++) acc[i][j] += a[i] * bv[j];
        }
        __syncthreads();
    }
    #pragma unroll
    for (int i = 0; i < TM; i++) {
        int gm = bm + ty * TM + i;
        #pragma unroll
        for (int j = 0; j < TN; j++) {
            int gn = bn + tx * TN + j;
            if (gn < N) {
                float v = acc[i][j];
                if (bias) v += bias[gn];
                if (GELU) v = gelu_f(v);
                if (RES) v += res[(size_t)gm * N + gn];
                C[(size_t)gm * N + gn] = v;
            }
        }
    }
}

// ---------------- Attention scores: S[bh, q, k] = (q . k) * 0.125 ----------------
__global__ void attn_qk_kernel(const float* __restrict__ qkv, float* __restrict__ S) {
    int bh = blockIdx.z;
    int b = bh / HH, h = bh % HH;
    int q0 = blockIdx.y * 64, k0 = blockIdx.x * 64;
    __shared__ float Qs[64][64];  // [d][q]
    __shared__ float Ks[64][64];  // [d][k]
    int tid = threadIdx.x;
    for (int i = tid; i < 1024; i += 256) {
        int r = i / 16, d4 = (i % 16) * 4;
        float4 v = make_float4(0.f, 0.f, 0.f, 0.f);
        if (q0 + r < NN)
            v = *(const float4*)(qkv + (size_t)(b * NN + q0 + r) * (3 * CC) + h * HD + d4);
        Qs[d4 + 0][r] = v.x; Qs[d4 + 1][r] = v.y; Qs[d4 + 2][r] = v.z; Qs[d4 + 3][r] = v.w;
        float4 w = make_float4(0.f, 0.f, 0.f, 0.f);
        if (k0 + r < NN)
            w = *(const float4*)(qkv + (size_t)(b * NN + k0 + r) * (3 * CC) + CC + h * HD + d4);
        Ks[d4 + 0][r] = w.x; Ks[d4 + 1][r] = w.y; Ks[d4 + 2][r] = w.z; Ks[d4 + 3][r] = w.w;
    }
    __syncthreads();
    int tx = tid % 16, ty = tid / 16;
    float acc[4][4] = {};
    #pragma unroll
    for (int d = 0; d < 64; d++) {
        float a[4], bb[4];
        #pragma unroll
        for (int i = 0; i < 4; i++) a[i] = Qs[d][ty * 4 + i];
        #pragma unroll
        for (int j = 0; j < 4; j++) bb[j] = Ks[d][tx * 4 + j];
        #pragma unroll
        for (int i = 0; i < 4; i++)
            #pragma unroll
            for (int j = 0; j < 4; j++) acc[i][j] += a[i] * bb[j];
    }
    #pragma unroll
    for (int i = 0; i < 4; i++) {
        int q = q0 + ty * 4 + i;
        #pragma unroll
        for (int j = 0; j < 4; j++) {
            int k = k0 + tx * 4 + j;
            if (q < NN && k < NN)
                S[((size_t)bh * NN + q) * NN + k] = acc[i][j] * 0.125f;
        }
    }
}

// ---------------- Row softmax over 197 entries ----------------
__global__ void softmax197_kernel(float* __restrict__ S) {
    size_t row = blockIdx.x;
    float* p = S + row * NN;
    int tid = threadIdx.x;
    __shared__ float red[256];
    float v = (tid < NN) ? p[tid] : -INFINITY;
    red[tid] = v; __syncthreads();
    for (int s = 128; s > 0; s >>= 1) {
        if (tid < s) red[tid] = fmaxf(red[tid], red[tid + s]);
        __syncthreads();
    }
    float mx = red[0]; __syncthreads();
    float e = (tid < NN) ? __expf(v - mx) : 0.0f;
    red[tid] = e; __syncthreads();
    for (int s = 128; s > 0; s >>= 1) {
        if (tid < s) red[tid] += red[tid + s];
        __syncthreads();
    }
    float inv = 1.0f / red[0];
    if (tid < NN) p[tid] = e * inv;
}

// ---------------- O = P @ V ----------------
__global__ void attn_av_kernel(const float* __restrict__ P, const float* __restrict__ qkv,
                               float* __restrict__ O) {
    int bh = blockIdx.y;
    int b = bh / HH, h = bh % HH;
    int q0 = blockIdx.x * 64;
    __shared__ float As[32][64];  // [k][q]
    __shared__ float Vs[32][64];  // [k][d]
    int tid = threadIdx.x, tx = tid % 16, ty = tid / 16;
    float acc[4][4] = {};
    for (int kt = 0; kt < NN; kt += 32) {
        for (int i = tid; i < 2048; i += 256) {
            int qi = i / 32, kk = i % 32;
            float v = 0.0f;
            if (q0 + qi < NN && kt + kk < NN)
                v = P[((size_t)bh * NN + q0 + qi) * NN + kt + kk];
            As[kk][qi] = v;
        }
        for (int i = tid; i < 512; i += 256) {
            int kk = i / 16, d4 = (i % 16) * 4;
            float4 v = make_float4(0.f, 0.f, 0.f, 0.f);
            if (kt + kk < NN)
                v = *(const float4*)(qkv + (size_t)(b * NN + kt + kk) * (3 * CC) + 2 * CC + h * HD + d4);
            *(float4*)&Vs[kk][d4] = v;
        }
        __syncthreads();
        #pragma unroll
        for (int kk = 0; kk < 32; kk++) {
            float a[4], bv[4];
            #pragma unroll
            for (int i = 0; i < 4; i++) a[i] = As[kk][ty * 4 + i];
            #pragma unroll
            for (int j = 0; j < 4; j++) bv[j] = Vs[kk][tx * 4 + j];
            #pragma unroll
            for (int i = 0; i < 4; i++)
                #pragma unroll
                for (int j = 0; j < 4; j++) acc[i][j] += a[i] * bv[j];
        }
        __syncthreads();
    }
    #pragma unroll
    for (int i = 0; i < 4; i++) {
        int q = q0 + ty * 4 + i;
        if (q < NN) {
            #pragma unroll
            for (int j = 0; j < 4; j++)
                O[((size_t)(b * NN + q)) * CC + h * HD + tx * 4 + j] = acc[i][j];
        }
    }
}

// ---------------- t[b,c,s] = ln3[b, 1+s, c] ----------------
__global__ void make_t_kernel(const float* __restrict__ ln3, float* __restrict__ t) {
    int idx = blockIdx.x * 256 + threadIdx.x;
    if (idx >= BB * OUTC * CNN) return;
    int s = idx % CNN;
    int c = (idx / CNN) % OUTC;
    int b = idx / (CNN * OUTC);
    t[idx] = ln3[((size_t)(b * NN + 1 + s)) * OUTC + c];
}

// ---------------- fused tiny channel attention (one block per (b,h)) ----------------
__global__ void chattn_kernel(const float* __restrict__ cqkv, float* __restrict__ co) {
    int b = blockIdx.x / CHH, h = blockIdx.x % CHH;
    int tid = threadIdx.x;
    __shared__ float Q[OUTC][CHD], Kk[OUTC][CHD], V[OUTC][CHD], S[OUTC][OUTC + 1];
    const float* base = cqkv + (size_t)b * OUTC * (3 * CNN);
    for (int i = tid; i < OUTC * CHD; i += 256) {
        int r = i / CHD, d = i % CHD;
        Q[r][d]  = base[r * (3 * CNN) + h * CHD + d];
        Kk[r][d] = base[r * (3 * CNN) + CNN + h * CHD + d];
        V[r][d]  = base[r * (3 * CNN) + 2 * CNN + h * CHD + d];
    }
    __syncthreads();
    const float sc = rsqrtf((float)CHD);
    for (int i = tid; i < OUTC * OUTC; i += 256) {
        int qi = i / OUTC, kj = i % OUTC;
        float s = 0.0f;
        #pragma unroll
        for (int d = 0; d < CHD; d++) s += Q[qi][d] * Kk[kj][d];
        S[qi][kj] = s * sc;
    }
    __syncthreads();
    if (tid < OUTC) {
        float mx = -INFINITY;
        #pragma unroll
        for (int j = 0; j < OUTC; j++) mx = fmaxf(mx, S[tid][j]);
        float sum = 0.0f;
        #pragma unroll
        for (int j = 0; j < OUTC; j++) { float e = __expf(S[tid][j] - mx); S[tid][j] = e; sum += e; }
        float inv = 1.0f / sum;
        #pragma unroll
        for (int j = 0; j < OUTC; j++) S[tid][j] *= inv;
    }
    __syncthreads();
    for (int i = tid; i < OUTC * CHD; i += 256) {
        int qi = i / CHD, d = i % CHD;
        float s = 0.0f;
        #pragma unroll
        for (int kk = 0; kk < OUTC; kk++) s += S[qi][kk] * V[kk][d];
        co[((size_t)(b * OUTC + qi)) * CNN + h * CHD + d] = s;
    }
}

// ---------------- x32 += concat([ln3 cls row, co2^T]) ----------------
__global__ void concat_add_kernel(const float* __restrict__ ln3, const float* __restrict__ co2,
                                  float* __restrict__ x32) {
    int idx = blockIdx.x * 256 + threadIdx.x;
    if (idx >= MROWS * OUTC) return;
    int c = idx % OUTC;
    int n = (idx / OUTC) % NN;
    int b = idx / (OUTC * NN);
    float add;
    if (n == 0) add = ln3[((size_t)b * NN) * OUTC + c];
    else        add = co2[((size_t)(b * OUTC + c)) * CNN + (n - 1)];
    x32[idx] += add;
}

// ---------------- launch ----------------
extern "C" void kernel_launch(void* const* d_in, const int* in_sizes, int n_in,
                              void* d_out, int out_size) {
    const float* x      = (const float*)d_in[0];
    const float* g1     = (const float*)d_in[1];
    const float* b1     = (const float*)d_in[2];
    const float* w_qkv  = (const float*)d_in[3];
    const float* w_proj = (const float*)d_in[4];
    const float* b_proj = (const float*)d_in[5];
    const float* g2     = (const float*)d_in[6];
    const float* b2     = (const float*)d_in[7];
    const float* w_fc1  = (const float*)d_in[8];
    const float* b_fc1  = (const float*)d_in[9];
    const float* w_fc2  = (const float*)d_in[10];
    const float* b_fc2  = (const float*)d_in[11];
    const float* g3     = (const float*)d_in[12];
    const float* b3     = (const float*)d_in[13];
    const float* w_cqkv = (const float*)d_in[14];
    const float* w_cproj= (const float*)d_in[15];
    const float* b_cproj= (const float*)d_in[16];
    const float* g4     = (const float*)d_in[17];
    const float* b4     = (const float*)d_in[18];
    const float* w_cfc1 = (const float*)d_in[19];
    const float* b_cfc1 = (const float*)d_in[20];
    const float* w_cfc2 = (const float*)d_in[21];
    const float* b_cfc2 = (const float*)d_in[22];
    float* out = (float*)d_out;

    float *p_ln, *p_qkv, *p_attn, *p_o, *p_x, *p_mlp, *p_x32, *p_ln32, *p_t, *p_cqkv, *p_co, *p_co2, *p_cmlp;
    cudaGetSymbolAddress((void**)&p_ln,   g_ln);
    cudaGetSymbolAddress((void**)&p_qkv,  g_qkv);
    cudaGetSymbolAddress((void**)&p_attn, g_attn);
    cudaGetSymbolAddress((void**)&p_o,    g_o);
    cudaGetSymbolAddress((void**)&p_x,    g_x);
    cudaGetSymbolAddress((void**)&p_mlp,  g_mlp);
    cudaGetSymbolAddress((void**)&p_x32,  g_x32);
    cudaGetSymbolAddress((void**)&p_ln32, g_ln32);
    cudaGetSymbolAddress((void**)&p_t,    g_t);
    cudaGetSymbolAddress((void**)&p_cqkv, g_cqkv);
    cudaGetSymbolAddress((void**)&p_co,   g_co);
    cudaGetSymbolAddress((void**)&p_co2,  g_co2);
    cudaGetSymbolAddress((void**)&p_cmlp, g_cmlp);

    const int M = MROWS;           // 25216 = 197 * 128
    // 1. LN1
    ln768_kernel<<<M, 256>>>(x, g1, b1, p_ln);
    // 2. qkv = ln1 @ w_qkv^T   [M, 2304]
    gemm_nt<128,128,16,8,8,false,false><<<dim3(18, M/128), 256>>>(p_ln, w_qkv, nullptr, nullptr, p_qkv, M, 3*CC, CC);
    // 3. scores
    attn_qk_kernel<<<dim3(4, 4, BB*HH), 256>>>(p_qkv, p_attn);
    // 4. softmax
    softmax197_kernel<<<BB*HH*NN, 256>>>(p_attn);
    // 5. O = P V
    attn_av_kernel<<<dim3(4, BB*HH), 256>>>(p_attn, p_qkv, p_o);
    // 6. x = x_in + O @ w_proj^T + b_proj
    gemm_nt<128,128,16,8,8,false,true><<<dim3(6, M/128), 256>>>(p_o, w_proj, b_proj, x, p_x, M, CC, CC);
    // 7. LN2
    ln768_kernel<<<M, 256>>>(p_x, g2, b2, p_ln);
    // 8. hidden = gelu(ln2 @ w_fc1^T + b_fc1)
    gemm_nt<128,128,16,8,8,true,false><<<dim3(24, M/128), 256>>>(p_ln, w_fc1, b_fc1, nullptr, p_mlp, M, MLPH, CC);
    // 9. x32 = hidden @ w_fc2^T + b_fc2
    gemm_nt<128,32,32,8,4,false,false><<<dim3(1, M/128), 128>>>(p_mlp, w_fc2, b_fc2, nullptr, p_x32, M, OUTC, MLPH);
    // 10. LN3
    ln32_kernel<<<M/8, 256>>>(p_x32, g3, b3, p_ln32);
    // 11. build t
    make_t_kernel<<<(BB*OUTC*CNN + 255)/256, 256>>>(p_ln32, p_t);
    // 12. cqkv = t @ w_cqkv^T   [4096, 588]
    gemm_nt<128,128,16,8,8,false,false><<<dim3(5, CMROWS/128), 256>>>(p_t, w_cqkv, nullptr, nullptr, p_cqkv, CMROWS, 3*CNN, CNN);
    // 13. channel attention
    chattn_kernel<<<BB*CHH, 256>>>(p_cqkv, p_co);
    // 14. co2 = co @ w_cproj^T + b_cproj  [4096, 196]
    gemm_nt<128,128,16,8,8,false,false><<<dim3(2, CMROWS/128), 256>>>(p_co, w_cproj, b_cproj, nullptr, p_co2, CMROWS, CNN, CNN);
    // 15. x32 += concat([cls, co2^T])
    concat_add_kernel<<<(M*OUTC + 255)/256, 256>>>(p_ln32, p_co2, p_x32);
    // 16. LN4
    ln32_kernel<<<M/8, 256>>>(p_x32, g4, b4, p_ln32);
    // 17. cmlp = gelu(ln4 @ w_cfc1^T + b_cfc1)   [M, 128]
    gemm_nt<128,128,16,8,8,true,false><<<dim3(1, M/128), 256>>>(p_ln32, w_cfc1, b_cfc1, nullptr, p_cmlp, M, CMLPH, OUTC);
    // 18. out = x32 + cmlp @ w_cfc2^T + b_cfc2   [M, 32]
    gemm_nt<128,32,32,8,4,false,true><<<dim3(1, M/128), 128>>>(p_cmlp, w_cfc2, b_cfc2, p_x32, out, M, OUTC, CMLPH);
}

// round 4
// speedup vs baseline: 2.1290x; 2.1290x over previous
#include <cuda_runtime.h>
#include <cuda_bf16.h>
#include <math.h>
#include <stdint.h>
#include <stddef.h>

// Problem constants
#define BB   128
#define NN   197
#define CC   768
#define HH   12
#define HD   64
#define OUTC 32
#define CHH  14
#define CHD  14
#define CNN  196
#define MLPH 3072
#define CMLPH 128
#define MROWS (BB*NN)          // 25216
#define CMROWS (BB*OUTC)       // 4096

// ---------------- scratch (device globals; no runtime allocation) ----------------
__device__ float g_ln  [MROWS*CC];
__device__ float g_qkv [MROWS*3*CC];
__device__ float g_attn[(size_t)BB*HH*NN*NN];
__device__ float g_o   [MROWS*CC];
__device__ float g_x   [MROWS*CC];
__device__ float g_mlp [(size_t)MROWS*MLPH];
__device__ float g_x32 [MROWS*OUTC];
__device__ float g_ln32[MROWS*OUTC];
__device__ float g_t   [BB*OUTC*CNN];
__device__ float g_cqkv[BB*OUTC*3*CNN];
__device__ float g_co  [BB*OUTC*CNN];
__device__ float g_co2 [BB*OUTC*CNN];
__device__ float g_cmlp[MROWS*CMLPH];
// bf16 split buffers (bf16x3: K' = 3K)
__device__ __nv_bfloat16 g_abf[(size_t)MROWS*3*MLPH];
__device__ __nv_bfloat16 g_wbf[(size_t)MLPH*3*CC];

__device__ __forceinline__ float gelu_f(float x) {
    return 0.5f * x * (1.0f + erff(x * 0.70710678118654752440f));
}

// ================= PTX helpers =================
__device__ __forceinline__ uint32_t smem_u32(const void* p) {
    uint32_t a;
    asm("{ .reg .u64 t; cvta.to.shared.u64 t, %1; cvt.u32.u64 %0, t; }" : "=r"(a) : "l"(p));
    return a;
}
#define CP_ASYNC16(d, s)    asm volatile("cp.async.cg.shared.global [%0], [%1], 16;" :: "r"(d), "l"(s))
#define CP_COMMIT()         asm volatile("cp.async.commit_group;" ::: "memory")
#define CP_WAIT1()          asm volatile("cp.async.wait_group 1;" ::: "memory")

__device__ __forceinline__ void ldm_x4(uint32_t* r, uint32_t addr) {
    asm volatile("ldmatrix.sync.aligned.m8n8.x4.shared.b16 {%0,%1,%2,%3}, [%4];"
        : "=r"(r[0]), "=r"(r[1]), "=r"(r[2]), "=r"(r[3]) : "r"(addr));
}
__device__ __forceinline__ void ldm_x2(uint32_t* r, uint32_t addr) {
    asm volatile("ldmatrix.sync.aligned.m8n8.x2.shared.b16 {%0,%1}, [%2];"
        : "=r"(r[0]), "=r"(r[1]) : "r"(addr));
}
__device__ __forceinline__ void mma_bf16(float* c, const uint32_t* a, const uint32_t* b) {
    asm volatile("mma.sync.aligned.m16n8k16.row.col.f32.bf16.bf16.f32 "
        "{%0,%1,%2,%3}, {%4,%5,%6,%7}, {%8,%9}, {%0,%1,%2,%3};"
        : "+f"(c[0]), "+f"(c[1]), "+f"(c[2]), "+f"(c[3])
        : "r"(a[0]), "r"(a[1]), "r"(a[2]), "r"(a[3]), "r"(b[0]), "r"(b[1]));
}
__device__ __forceinline__ uint32_t swz(uint32_t off) { return off ^ ((off >> 3) & 0x70); }

// ================= bf16x3 split conversions =================
// activations: [hi | hi | lo]
__global__ void conv_act(const float* __restrict__ in, __nv_bfloat16* __restrict__ out,
                         int Mr, int K) {
    long long idx = (long long)blockIdx.x * 256 + threadIdx.x;
    if (idx >= (long long)Mr * K) return;
    int m = (int)(idx / K), k = (int)(idx % K);
    float v = in[idx];
    __nv_bfloat16 hi = __float2bfloat16(v);
    __nv_bfloat16 lo = __float2bfloat16(v - __bfloat162float(hi));
    __nv_bfloat16* row = out + (size_t)m * 3 * K;
    row[k] = hi; row[K + k] = hi; row[2 * K + k] = lo;
}
// weights: [hi | lo | hi]
__global__ void conv_wt(const float* __restrict__ in, __nv_bfloat16* __restrict__ out,
                        int Nr, int K) {
    long long idx = (long long)blockIdx.x * 256 + threadIdx.x;
    if (idx >= (long long)Nr * K) return;
    int n = (int)(idx / K), k = (int)(idx % K);
    float v = in[idx];
    __nv_bfloat16 hi = __float2bfloat16(v);
    __nv_bfloat16 lo = __float2bfloat16(v - __bfloat162float(hi));
    __nv_bfloat16* row = out + (size_t)n * 3 * K;
    row[k] = hi; row[K + k] = lo; row[2 * K + k] = hi;
}

// ================= mma.sync bf16 NT GEMM =================
// C[M,N] = epi(Abf[M,Kp] * Bbf[N,Kp]^T).  M%128==0, N%BN==0, Kp%64==0.
// 256 threads, 8 warps in 4(m) x 2(n) grid. Warp tile 32 x BN/2.
template<int BN, bool GELU, bool RES>
__global__ void __launch_bounds__(256)
gemm_mma(const __nv_bfloat16* __restrict__ A, const __nv_bfloat16* __restrict__ Bw,
         const float* __restrict__ bias, const float* __restrict__ res,
         float* __restrict__ C, int M, int N, int Kp) {
    constexpr int A_BYTES = 128 * 128;   // 128 rows x 64 bf16
    constexpr int B_BYTES = BN * 128;
    constexpr int STAGE = A_BYTES + B_BYTES;
    constexpr int NSTG = 3;
    constexpr int WN = BN / 2;           // warp n-tile
    constexpr int MF = 2;                // 32/16
    constexpr int NF = WN / 8;

    extern __shared__ char smraw[];
    char* sm = (char*)(((uintptr_t)smraw + 1023) & ~(uintptr_t)1023);
    uint32_t smb = smem_u32(sm);

    int tid = threadIdx.x, wid = tid >> 5, lane = tid & 31;
    int wm = wid & 3, wn = wid >> 2;
    int bm = blockIdx.y * 128, bn = blockIdx.x * BN;
    const __nv_bfloat16* Ab = A + (size_t)bm * Kp;
    const __nv_bfloat16* Bb = Bw + (size_t)bn * Kp;

    const int nk = Kp >> 6;

    auto load_tile = [&](int kt, int s) {
        int k0 = kt << 6;
        uint32_t sa = smb + s * STAGE;
        #pragma unroll
        for (int i = 0; i < (128 * 8) / 256; i++) {
            int idx = tid + i * 256;
            int r = idx >> 3, cb = (idx & 7) << 4;
            CP_ASYNC16(sa + swz((r << 7) | cb),
                       (const char*)(Ab + (size_t)r * Kp + k0) + cb);
        }
        uint32_t sb = sa + A_BYTES;
        #pragma unroll
        for (int i = 0; i < (BN * 8 + 255) / 256; i++) {
            int idx = tid + i * 256;
            if (BN * 8 % 256 == 0 || idx < BN * 8) {
                int r = idx >> 3, cb = (idx & 7) << 4;
                CP_ASYNC16(sb + swz((r << 7) | cb),
                           (const char*)(Bb + (size_t)r * Kp + k0) + cb);
            }
        }
    };

    float acc[MF][NF][4];
    #pragma unroll
    for (int i = 0; i < MF; i++)
        #pragma unroll
        for (int j = 0; j < NF; j++)
            #pragma unroll
            for (int e = 0; e < 4; e++) acc[i][j][e] = 0.0f;

    // prologue
    load_tile(0, 0); CP_COMMIT();
    if (nk > 1) load_tile(1, 1);
    CP_COMMIT();

    // precomputed ldmatrix lane-address components
    int a_mi = lane >> 3, a_r = lane & 7;           // A: matrix idx, row
    int b_mi = (lane >> 3) & 1, b_r = lane & 7;     // B: lanes 0-15 used

    for (int kt = 0; kt < nk; kt++) {
        CP_WAIT1();
        __syncthreads();
        int s = kt % NSTG;
        uint32_t sa = smb + s * STAGE;
        uint32_t sb = sa + A_BYTES;

        #pragma unroll
        for (int ks = 0; ks < 4; ks++) {
            uint32_t afr[MF][4];
            #pragma unroll
            for (int mf = 0; mf < MF; mf++) {
                int row = wm * 32 + mf * 16 + ((a_mi & 1) << 3) + a_r;
                int unit = ks * 2 + (a_mi >> 1);
                ldm_x4(afr[mf], sa + swz((row << 7) | (unit << 4)));
            }
            #pragma unroll
            for (int nf = 0; nf < NF; nf++) {
                uint32_t bfr[2];
                int row = wn * WN + nf * 8 + b_r;
                int unit = ks * 2 + b_mi;
                ldm_x2(bfr, sb + swz((row << 7) | (unit << 4)));
                #pragma unroll
                for (int mf = 0; mf < MF; mf++)
                    mma_bf16(acc[mf][nf], afr[mf], bfr);
            }
        }
        __syncthreads();
        if (kt + 2 < nk) load_tile(kt + 2, (kt + 2) % NSTG);
        CP_COMMIT();
    }

    // epilogue: c-frag rows lane/4 (+8), cols (lane%4)*2
    int cr = lane >> 2, cc2 = (lane & 3) << 1;
    #pragma unroll
    for (int mf = 0; mf < MF; mf++) {
        #pragma unroll
        for (int half = 0; half < 2; half++) {
            int gm = bm + wm * 32 + mf * 16 + cr + half * 8;
            #pragma unroll
            for (int nf = 0; nf < NF; nf++) {
                int gn = bn + wn * WN + nf * 8 + cc2;
                float v0 = acc[mf][nf][half * 2 + 0];
                float v1 = acc[mf][nf][half * 2 + 1];
                if (bias) { v0 += __ldg(&bias[gn]); v1 += __ldg(&bias[gn + 1]); }
                if (GELU) { v0 = gelu_f(v0); v1 = gelu_f(v1); }
                if (RES) {
                    float2 rv = *(const float2*)(res + (size_t)gm * N + gn);
                    v0 += rv.x; v1 += rv.y;
                }
                *(float2*)(C + (size_t)gm * N + gn) = make_float2(v0, v1);
            }
        }
    }
}

// ---------------- LayerNorm D=768 ----------------
__global__ void ln768_kernel(const float* __restrict__ x, const float* __restrict__ g,
                             const float* __restrict__ b, float* __restrict__ out) {
    int row = blockIdx.x;
    const float* p = x + (size_t)row * CC;
    float* o = out + (size_t)row * CC;
    int tid = threadIdx.x;
    float v0 = p[tid], v1 = p[tid + 256], v2 = p[tid + 512];
    float s = v0 + v1 + v2;
    float sq = v0 * v0 + v1 * v1 + v2 * v2;
    __shared__ float rs[256], rq[256];
    rs[tid] = s; rq[tid] = sq; __syncthreads();
    for (int st = 128; st > 0; st >>= 1) {
        if (tid < st) { rs[tid] += rs[tid + st]; rq[tid] += rq[tid + st]; }
        __syncthreads();
    }
    float mean = rs[0] * (1.0f / CC);
    float var  = rq[0] * (1.0f / CC) - mean * mean;
    float inv = rsqrtf(var + 1e-5f);
    o[tid]       = (v0 - mean) * inv * g[tid]       + b[tid];
    o[tid + 256] = (v1 - mean) * inv * g[tid + 256] + b[tid + 256];
    o[tid + 512] = (v2 - mean) * inv * g[tid + 512] + b[tid + 512];
}

// ---------------- LayerNorm D=32 ----------------
__global__ void ln32_kernel(const float* __restrict__ x, const float* __restrict__ g,
                            const float* __restrict__ b, float* __restrict__ out) {
    int row = blockIdx.x * 8 + threadIdx.x / 32;
    int lane = threadIdx.x & 31;
    float v = x[(size_t)row * OUTC + lane];
    float s = v, sq = v * v;
    #pragma unroll
    for (int o = 16; o > 0; o >>= 1) {
        s  += __shfl_xor_sync(0xffffffff, s, o);
        sq += __shfl_xor_sync(0xffffffff, sq, o);
    }
    float mean = s * (1.0f / OUTC);
    float var  = sq * (1.0f / OUTC) - mean * mean;
    float inv = rsqrtf(var + 1e-5f);
    out[(size_t)row * OUTC + lane] = (v - mean) * inv * g[lane] + b[lane];
}

// ---------------- fp32 SIMT GEMM (small channel GEMMs) ----------------
template<int BM, int BN, int BK, int TM, int TN, bool GELU, bool RES>
__global__ void gemm_nt(const float* __restrict__ A, const float* __restrict__ Bw,
                        const float* __restrict__ bias, const float* __restrict__ res,
                        float* __restrict__ C, int M, int N, int K) {
    constexpr int THREADS = (BM / TM) * (BN / TN);
    __shared__ float As[BK][BM];
    __shared__ float Bs[BK][BN];
    int tid = threadIdx.x;
    int bm = blockIdx.y * BM, bn = blockIdx.x * BN;
    int tx = tid % (BN / TN), ty = tid / (BN / TN);
    float acc[TM][TN];
    #pragma unroll
    for (int i = 0; i < TM; i++)
        #pragma unroll
        for (int j = 0; j < TN; j++) acc[i][j] = 0.0f;
    constexpr int A4 = BM * BK / 4;
    constexpr int B4 = BN * BK / 4;
    for (int k0 = 0; k0 < K; k0 += BK) {
        #pragma unroll
        for (int i = tid; i < A4; i += THREADS) {
            int row = i / (BK / 4);
            int kk  = (i % (BK / 4)) * 4;
            float4 v = make_float4(0.f, 0.f, 0.f, 0.f);
            if (k0 + kk < K) v = *(const float4*)(A + (size_t)(bm + row) * K + k0 + kk);
            As[kk + 0][row] = v.x; As[kk + 1][row] = v.y;
            As[kk + 2][row] = v.z; As[kk + 3][row] = v.w;
        }
        #pragma unroll
        for (int i = tid; i < B4; i += THREADS) {
            int row = i / (BK / 4);
            int kk  = (i % (BK / 4)) * 4;
            float4 v = make_float4(0.f, 0.f, 0.f, 0.f);
            if (bn + row < N && k0 + kk < K)
                v = *(const float4*)(Bw + (size_t)(bn + row) * K + k0 + kk);
            Bs[kk + 0][row] = v.x; Bs[kk + 1][row] = v.y;
            Bs[kk + 2][row] = v.z; Bs[kk + 3][row] = v.w;
        }
        __syncthreads();
        #pragma unroll
        for (int kk = 0; kk < BK; kk++) {
            float a[TM], bv[TN];
            #pragma unroll
            for (int i = 0; i < TM; i++) a[i] = As[kk][ty * TM + i];
            #pragma unroll
            for (int j = 0; j < TN; j++) bv[j] = Bs[kk][tx * TN + j];
            #pragma unroll
            for (int i = 0; i < TM; i++)
                #pragma unroll
                for (int j = 0; j < TN; j++) acc[i][j] += a[i] * bv[j];
        }
        __syncthreads();
    }
    #pragma unroll
    for (int i = 0; i < TM; i++) {
        int gm = bm + ty * TM + i;
        #pragma unroll
        for (int j = 0; j < TN; j++) {
            int gn = bn + tx * TN + j;
            if (gn < N) {
                float v = acc[i][j];
                if (bias) v += bias[gn];
                if (GELU) v = gelu_f(v);
                if (RES) v += res[(size_t)gm * N + gn];
                C[(size_t)gm * N + gn] = v;
            }
        }
    }
}

// ---------------- Attention scores ----------------
__global__ void attn_qk_kernel(const float* __restrict__ qkv, float* __restrict__ S) {
    int bh = blockIdx.z;
    int b = bh / HH, h = bh % HH;
    int q0 = blockIdx.y * 64, k0 = blockIdx.x * 64;
    __shared__ float Qs[64][64];
    __shared__ float Ks[64][64];
    int tid = threadIdx.x;
    for (int i = tid; i < 1024; i += 256) {
        int r = i / 16, d4 = (i % 16) * 4;
        float4 v = make_float4(0.f, 0.f, 0.f, 0.f);
        if (q0 + r < NN)
            v = *(const float4*)(qkv + (size_t)(b * NN + q0 + r) * (3 * CC) + h * HD + d4);
        Qs[d4 + 0][r] = v.x; Qs[d4 + 1][r] = v.y; Qs[d4 + 2][r] = v.z; Qs[d4 + 3][r] = v.w;
        float4 w = make_float4(0.f, 0.f, 0.f, 0.f);
        if (k0 + r < NN)
            w = *(const float4*)(qkv + (size_t)(b * NN + k0 + r) * (3 * CC) + CC + h * HD + d4);
        Ks[d4 + 0][r] = w.x; Ks[d4 + 1][r] = w.y; Ks[d4 + 2][r] = w.z; Ks[d4 + 3][r] = w.w;
    }
    __syncthreads();
    int tx = tid % 16, ty = tid / 16;
    float acc[4][4] = {};
    #pragma unroll
    for (int d = 0; d < 64; d++) {
        float a[4], bb[4];
        #pragma unroll
        for (int i = 0; i < 4; i++) a[i] = Qs[d][ty * 4 + i];
        #pragma unroll
        for (int j = 0; j < 4; j++) bb[j] = Ks[d][tx * 4 + j];
        #pragma unroll
        for (int i = 0; i < 4; i++)
            #pragma unroll
            for (int j = 0; j < 4; j++) acc[i][j] += a[i] * bb[j];
    }
    #pragma unroll
    for (int i = 0; i < 4; i++) {
        int q = q0 + ty * 4 + i;
        #pragma unroll
        for (int j = 0; j < 4; j++) {
            int k = k0 + tx * 4 + j;
            if (q < NN && k < NN)
                S[((size_t)bh * NN + q) * NN + k] = acc[i][j] * 0.125f;
        }
    }
}

// ---------------- warp-per-row softmax over 197 ----------------
__global__ void softmax197_warp(float* __restrict__ S) {
    int row = blockIdx.x * 8 + (threadIdx.x >> 5);
    int lane = threadIdx.x & 31;
    float* p = S + (size_t)row * NN;
    float v[7];
    float mx = -INFINITY;
    #pragma unroll
    for (int j = 0; j < 7; j++) {
        int idx = lane + 32 * j;
        v[j] = (idx < NN) ? p[idx] : -INFINITY;
        mx = fmaxf(mx, v[j]);
    }
    #pragma unroll
    for (int o = 16; o > 0; o >>= 1) mx = fmaxf(mx, __shfl_xor_sync(0xffffffff, mx, o));
    float sum = 0.0f;
    #pragma unroll
    for (int j = 0; j < 7; j++) { v[j] = __expf(v[j] - mx); sum += (lane + 32 * j < NN) ? v[j] : 0.0f; }
    #pragma unroll
    for (int o = 16; o > 0; o >>= 1) sum += __shfl_xor_sync(0xffffffff, sum, o);
    float inv = 1.0f / sum;
    #pragma unroll
    for (int j = 0; j < 7; j++) {
        int idx = lane + 32 * j;
        if (idx < NN) p[idx] = v[j] * inv;
    }
}

// ---------------- O = P @ V ----------------
__global__ void attn_av_kernel(const float* __restrict__ P, const float* __restrict__ qkv,
                               float* __restrict__ O) {
    int bh = blockIdx.y;
    int b = bh / HH, h = bh % HH;
    int q0 = blockIdx.x * 64;
    __shared__ float As[32][64];
    __shared__ float Vs[32][64];
    int tid = threadIdx.x, tx = tid % 16, ty = tid / 16;
    float acc[4][4] = {};
    for (int kt = 0; kt < NN; kt += 32) {
        for (int i = tid; i < 2048; i += 256) {
            int qi = i / 32, kk = i % 32;
            float v = 0.0f;
            if (q0 + qi < NN && kt + kk < NN)
                v = P[((size_t)bh * NN + q0 + qi) * NN + kt + kk];
            As[kk][qi] = v;
        }
        for (int i = tid; i < 512; i += 256) {
            int kk = i / 16, d4 = (i % 16) * 4;
            float4 v = make_float4(0.f, 0.f, 0.f, 0.f);
            if (kt + kk < NN)
                v = *(const float4*)(qkv + (size_t)(b * NN + kt + kk) * (3 * CC) + 2 * CC + h * HD + d4);
            *(float4*)&Vs[kk][d4] = v;
        }
        __syncthreads();
        #pragma unroll
        for (int kk = 0; kk < 32; kk++) {
            float a[4], bv[4];
            #pragma unroll
            for (int i = 0; i < 4; i++) a[i] = As[kk][ty * 4 + i];
            #pragma unroll
            for (int j = 0; j < 4; j++) bv[j] = Vs[kk][tx * 4 + j];
            #pragma unroll
            for (int i = 0; i < 4; i++)
                #pragma unroll
                for (int j = 0; j < 4; j++) acc[i][j] += a[i] * bv[j];
        }
        __syncthreads();
    }
    #pragma unroll
    for (int i = 0; i < 4; i++) {
        int q = q0 + ty * 4 + i;
        if (q < NN) {
            #pragma unroll
            for (int j = 0; j < 4; j++)
                O[((size_t)(b * NN + q)) * CC + h * HD + tx * 4 + j] = acc[i][j];
        }
    }
}

// ---------------- t[b,c,s] = ln3[b, 1+s, c] ----------------
__global__ void make_t_kernel(const float* __restrict__ ln3, float* __restrict__ t) {
    int idx = blockIdx.x * 256 + threadIdx.x;
    if (idx >= BB * OUTC * CNN) return;
    int s = idx % CNN;
    int c = (idx / CNN) % OUTC;
    int b = idx / (CNN * OUTC);
    t[idx] = ln3[((size_t)(b * NN + 1 + s)) * OUTC + c];
}

// ---------------- tiny channel attention ----------------
__global__ void chattn_kernel(const float* __restrict__ cqkv, float* __restrict__ co) {
    int b = blockIdx.x / CHH, h = blockIdx.x % CHH;
    int tid = threadIdx.x;
    __shared__ float Q[OUTC][CHD], Kk[OUTC][CHD], V[OUTC][CHD], S[OUTC][OUTC + 1];
    const float* base = cqkv + (size_t)b * OUTC * (3 * CNN);
    for (int i = tid; i < OUTC * CHD; i += 256) {
        int r = i / CHD, d = i % CHD;
        Q[r][d]  = base[r * (3 * CNN) + h * CHD + d];
        Kk[r][d] = base[r * (3 * CNN) + CNN + h * CHD + d];
        V[r][d]  = base[r * (3 * CNN) + 2 * CNN + h * CHD + d];
    }
    __syncthreads();
    const float sc = rsqrtf((float)CHD);
    for (int i = tid; i < OUTC * OUTC; i += 256) {
        int qi = i / OUTC, kj = i % OUTC;
        float s = 0.0f;
        #pragma unroll
        for (int d = 0; d < CHD; d++) s += Q[qi][d] * Kk[kj][d];
        S[qi][kj] = s * sc;
    }
    __syncthreads();
    if (tid < OUTC) {
        float mx = -INFINITY;
        #pragma unroll
        for (int j = 0; j < OUTC; j++) mx = fmaxf(mx, S[tid][j]);
        float sum = 0.0f;
        #pragma unroll
        for (int j = 0; j < OUTC; j++) { float e = __expf(S[tid][j] - mx); S[tid][j] = e; sum += e; }
        float inv = 1.0f / sum;
        #pragma unroll
        for (int j = 0; j < OUTC; j++) S[tid][j] *= inv;
    }
    __syncthreads();
    for (int i = tid; i < OUTC * CHD; i += 256) {
        int qi = i / CHD, d = i % CHD;
        float s = 0.0f;
        #pragma unroll
        for (int kk = 0; kk < OUTC; kk++) s += S[qi][kk] * V[kk][d];
        co[((size_t)(b * OUTC + qi)) * CNN + h * CHD + d] = s;
    }
}

// ---------------- x32 += concat([ln3 cls, co2^T]) ----------------
__global__ void concat_add_kernel(const float* __restrict__ ln3, const float* __restrict__ co2,
                                  float* __restrict__ x32) {
    int idx = blockIdx.x * 256 + threadIdx.x;
    if (idx >= MROWS * OUTC) return;
    int c = idx % OUTC;
    int n = (idx / OUTC) % NN;
    int b = idx / (OUTC * NN);
    float add;
    if (n == 0) add = ln3[((size_t)b * NN) * OUTC + c];
    else        add = co2[((size_t)(b * OUTC + c)) * CNN + (n - 1)];
    x32[idx] += add;
}

// ---------------- launch ----------------
static inline int cdiv(long long a, int b) { return (int)((a + b - 1) / b); }

extern "C" void kernel_launch(void* const* d_in, const int* in_sizes, int n_in,
                              void* d_out, int out_size) {
    const float* x      = (const float*)d_in[0];
    const float* g1     = (const float*)d_in[1];
    const float* b1     = (const float*)d_in[2];
    const float* w_qkv  = (const float*)d_in[3];
    const float* w_proj = (const float*)d_in[4];
    const float* b_proj = (const float*)d_in[5];
    const float* g2     = (const float*)d_in[6];
    const float* b2     = (const float*)d_in[7];
    const float* w_fc1  = (const float*)d_in[8];
    const float* b_fc1  = (const float*)d_in[9];
    const float* w_fc2  = (const float*)d_in[10];
    const float* b_fc2  = (const float*)d_in[11];
    const float* g3     = (const float*)d_in[12];
    const float* b3     = (const float*)d_in[13];
    const float* w_cqkv = (const float*)d_in[14];
    const float* w_cproj= (const float*)d_in[15];
    const float* b_cproj= (const float*)d_in[16];
    const float* g4     = (const float*)d_in[17];
    const float* b4     = (const float*)d_in[18];
    const float* w_cfc1 = (const float*)d_in[19];
    const float* b_cfc1 = (const float*)d_in[20];
    const float* w_cfc2 = (const float*)d_in[21];
    const float* b_cfc2 = (const float*)d_in[22];
    float* out = (float*)d_out;

    float *p_ln, *p_qkv, *p_attn, *p_o, *p_x, *p_mlp, *p_x32, *p_ln32, *p_t, *p_cqkv, *p_co, *p_co2, *p_cmlp;
    __nv_bfloat16 *p_abf, *p_wbf;
    cudaGetSymbolAddress((void**)&p_ln,   g_ln);
    cudaGetSymbolAddress((void**)&p_qkv,  g_qkv);
    cudaGetSymbolAddress((void**)&p_attn, g_attn);
    cudaGetSymbolAddress((void**)&p_o,    g_o);
    cudaGetSymbolAddress((void**)&p_x,    g_x);
    cudaGetSymbolAddress((void**)&p_mlp,  g_mlp);
    cudaGetSymbolAddress((void**)&p_x32,  g_x32);
    cudaGetSymbolAddress((void**)&p_ln32, g_ln32);
    cudaGetSymbolAddress((void**)&p_t,    g_t);
    cudaGetSymbolAddress((void**)&p_cqkv, g_cqkv);
    cudaGetSymbolAddress((void**)&p_co,   g_co);
    cudaGetSymbolAddress((void**)&p_co2,  g_co2);
    cudaGetSymbolAddress((void**)&p_cmlp, g_cmlp);
    cudaGetSymbolAddress((void**)&p_abf,  g_abf);
    cudaGetSymbolAddress((void**)&p_wbf,  g_wbf);

    const int SM128 = 3 * (128 * 128 + 128 * 128) + 1024;   // 99328
    const int SM32  = 3 * (128 * 128 + 32 * 128) + 1024;    // 62464
    cudaFuncSetAttribute(gemm_mma<128, false, false>, cudaFuncAttributeMaxDynamicSharedMemorySize, SM128);
    cudaFuncSetAttribute(gemm_mma<128, false, true >, cudaFuncAttributeMaxDynamicSharedMemorySize, SM128);
    cudaFuncSetAttribute(gemm_mma<128, true,  false>, cudaFuncAttributeMaxDynamicSharedMemorySize, SM128);
    cudaFuncSetAttribute(gemm_mma<32,  false, false>, cudaFuncAttributeMaxDynamicSharedMemorySize, SM32);
    cudaFuncSetAttribute(gemm_mma<32,  false, true >, cudaFuncAttributeMaxDynamicSharedMemorySize, SM32);

    const int M = MROWS;  // 25216 = 128*197
    const int MB = M / 128;

    // 1. LN1
    ln768_kernel<<<M, 256>>>(x, g1, b1, p_ln);
    // 2. qkv = ln1 @ w_qkv^T  (bf16x3)
    conv_act<<<cdiv((long long)M * CC, 256), 256>>>(p_ln, p_abf, M, CC);
    conv_wt <<<cdiv((long long)3 * CC * CC, 256), 256>>>(w_qkv, p_wbf, 3 * CC, CC);
    gemm_mma<128, false, false><<<dim3(18, MB), 256, SM128>>>(p_abf, p_wbf, nullptr, nullptr, p_qkv, M, 3 * CC, 3 * CC);
    // 3-5. attention
    attn_qk_kernel<<<dim3(4, 4, BB * HH), 256>>>(p_qkv, p_attn);
    softmax197_warp<<<BB * HH * NN / 8, 256>>>(p_attn);
    attn_av_kernel<<<dim3(4, BB * HH), 256>>>(p_attn, p_qkv, p_o);
    // 6. x = x_in + O @ w_proj^T + b_proj
    conv_act<<<cdiv((long long)M * CC, 256), 256>>>(p_o, p_abf, M, CC);
    conv_wt <<<cdiv((long long)CC * CC, 256), 256>>>(w_proj, p_wbf, CC, CC);
    gemm_mma<128, false, true><<<dim3(6, MB), 256, SM128>>>(p_abf, p_wbf, b_proj, x, p_x, M, CC, 3 * CC);
    // 7. LN2
    ln768_kernel<<<M, 256>>>(p_x, g2, b2, p_ln);
    // 8. hidden = gelu(ln2 @ w_fc1^T + b_fc1)
    conv_act<<<cdiv((long long)M * CC, 256), 256>>>(p_ln, p_abf, M, CC);
    conv_wt <<<cdiv((long long)MLPH * CC, 256), 256>>>(w_fc1, p_wbf, MLPH, CC);
    gemm_mma<128, true, false><<<dim3(24, MB), 256, SM128>>>(p_abf, p_wbf, b_fc1, nullptr, p_mlp, M, MLPH, 3 * CC);
    // 9. x32 = hidden @ w_fc2^T + b_fc2
    conv_act<<<cdiv((long long)M * MLPH, 256), 256>>>(p_mlp, p_abf, M, MLPH);
    conv_wt <<<cdiv((long long)OUTC * MLPH, 256), 256>>>(w_fc2, p_wbf, OUTC, MLPH);
    gemm_mma<32, false, false><<<dim3(1, MB), 256, SM32>>>(p_abf, p_wbf, b_fc2, nullptr, p_x32, M, OUTC, 3 * MLPH);
    // 10. LN3
    ln32_kernel<<<M / 8, 256>>>(p_x32, g3, b3, p_ln32);
    // 11. build t
    make_t_kernel<<<(BB * OUTC * CNN + 255) / 256, 256>>>(p_ln32, p_t);
    // 12. cqkv = t @ w_cqkv^T
    gemm_nt<128, 128, 16, 8, 8, false, false><<<dim3(5, CMROWS / 128), 256>>>(p_t, w_cqkv, nullptr, nullptr, p_cqkv, CMROWS, 3 * CNN, CNN);
    // 13. channel attention
    chattn_kernel<<<BB * CHH, 256>>>(p_cqkv, p_co);
    // 14. co2 = co @ w_cproj^T + b_cproj
    gemm_nt<128, 128, 16, 8, 8, false, false><<<dim3(2, CMROWS / 128), 256>>>(p_co, w_cproj, b_cproj, nullptr, p_co2, CMROWS, CNN, CNN);
    // 15. x32 += concat
    concat_add_kernel<<<(M * OUTC + 255) / 256, 256>>>(p_ln32, p_co2, p_x32);
    // 16. LN4
    ln32_kernel<<<M / 8, 256>>>(p_x32, g4, b4, p_ln32);
    // 17. cmlp = gelu(ln4 @ w_cfc1^T + b_cfc1)
    gemm_nt<128, 128, 16, 8, 8, true, false><<<dim3(1, MB), 256>>>(p_ln32, w_cfc1, b_cfc1, nullptr, p_cmlp, M, CMLPH, OUTC);
    // 18. out = x32 + cmlp @ w_cfc2^T + b_cfc2  (bf16x3)
    conv_act<<<cdiv((long long)M * CMLPH, 256), 256>>>(p_cmlp, p_abf, M, CMLPH);
    conv_wt <<<cdiv((long long)OUTC * CMLPH, 256), 256>>>(w_cfc2, p_wbf, OUTC, CMLPH);
    gemm_mma<32, false, true><<<dim3(1, MB), 256, SM32>>>(p_abf, p_wbf, b_cfc2, p_x32, out, M, OUTC, 3 * CMLPH);
}

// round 5
// speedup vs baseline: 2.5044x; 1.1763x over previous
#include <cuda_runtime.h>
#include <cuda_bf16.h>
#include <math.h>
#include <stdint.h>
#include <stddef.h>

// Problem constants
#define BB   128
#define NN   197
#define CC   768
#define HH   12
#define HD   64
#define OUTC 32
#define CHH  14
#define CHD  14
#define CNN  196
#define MLPH 3072
#define CMLPH 128
#define MROWS (BB*NN)          // 25216
#define CMROWS (BB*OUTC)       // 4096

// ---------------- scratch ----------------
__device__ float g_ln  [MROWS*CC];
__device__ float g_qkv [MROWS*3*CC];
__device__ float g_attn[(size_t)BB*HH*NN*NN];
__device__ float g_o   [MROWS*CC];
__device__ float g_x   [MROWS*CC];
__device__ float g_mlp [(size_t)MROWS*MLPH];
__device__ float g_x32 [MROWS*OUTC];
__device__ float g_ln32[MROWS*OUTC];
__device__ float g_t   [BB*OUTC*CNN];
__device__ float g_cqkv[BB*OUTC*3*CNN];
__device__ float g_co  [BB*OUTC*CNN];
__device__ float g_co2 [BB*OUTC*CNN];
__device__ float g_cmlp[MROWS*CMLPH];
__device__ __nv_bfloat16 g_abf[(size_t)MROWS*3*MLPH];
__device__ __nv_bfloat16 g_wbf[(size_t)MLPH*3*CC];

__device__ __forceinline__ float gelu_f(float x) {
    return 0.5f * x * (1.0f + erff(x * 0.70710678118654752440f));
}

// ================= PTX helpers =================
__device__ __forceinline__ uint32_t smem_u32(const void* p) {
    uint32_t a;
    asm("{ .reg .u64 t; cvta.to.shared.u64 t, %1; cvt.u32.u64 %0, t; }" : "=r"(a) : "l"(p));
    return a;
}
#define CP_ASYNC16(d, s)    asm volatile("cp.async.cg.shared.global [%0], [%1], 16;" :: "r"(d), "l"(s))
#define CP_COMMIT()         asm volatile("cp.async.commit_group;" ::: "memory")
#define CP_WAIT1()          asm volatile("cp.async.wait_group 1;" ::: "memory")

__device__ __forceinline__ void ldm_x4(uint32_t* r, uint32_t addr) {
    asm volatile("ldmatrix.sync.aligned.m8n8.x4.shared.b16 {%0,%1,%2,%3}, [%4];"
        : "=r"(r[0]), "=r"(r[1]), "=r"(r[2]), "=r"(r[3]) : "r"(addr));
}
__device__ __forceinline__ void mma_bf16(float* c, const uint32_t* a, const uint32_t* b) {
    asm volatile("mma.sync.aligned.m16n8k16.row.col.f32.bf16.bf16.f32 "
        "{%0,%1,%2,%3}, {%4,%5,%6,%7}, {%8,%9}, {%0,%1,%2,%3};"
        : "+f"(c[0]), "+f"(c[1]), "+f"(c[2]), "+f"(c[3])
        : "r"(a[0]), "r"(a[1]), "r"(a[2]), "r"(a[3]), "r"(b[0]), "r"(b[1]));
}
__device__ __forceinline__ uint32_t swz(uint32_t off) { return off ^ ((off >> 3) & 0x70); }

// ================= bf16x3 split conversions (vectorized) =================
// activations: [hi | hi | lo]
__global__ void conv_act(const float* __restrict__ in, __nv_bfloat16* __restrict__ out,
                         int Mr, int K) {
    long long idx = (long long)blockIdx.x * 256 + threadIdx.x;
    long long tot = (long long)Mr * (K / 4);
    if (idx >= tot) return;
    int m = (int)(idx / (K / 4)), k = (int)(idx % (K / 4)) * 4;
    float4 v = *(const float4*)(in + (size_t)m * K + k);
    __nv_bfloat16 h0 = __float2bfloat16(v.x), h1 = __float2bfloat16(v.y);
    __nv_bfloat16 h2 = __float2bfloat16(v.z), h3 = __float2bfloat16(v.w);
    __nv_bfloat162 hp0 = __nv_bfloat162(h0, h1), hp1 = __nv_bfloat162(h2, h3);
    __nv_bfloat162 lp0 = __nv_bfloat162(__float2bfloat16(v.x - __bfloat162float(h0)),
                                        __float2bfloat16(v.y - __bfloat162float(h1)));
    __nv_bfloat162 lp1 = __nv_bfloat162(__float2bfloat16(v.z - __bfloat162float(h2)),
                                        __float2bfloat16(v.w - __bfloat162float(h3)));
    __nv_bfloat16* row = out + (size_t)m * 3 * K;
    *(__nv_bfloat162*)(row + k) = hp0;           *(__nv_bfloat162*)(row + k + 2) = hp1;
    *(__nv_bfloat162*)(row + K + k) = hp0;       *(__nv_bfloat162*)(row + K + k + 2) = hp1;
    *(__nv_bfloat162*)(row + 2 * K + k) = lp0;   *(__nv_bfloat162*)(row + 2 * K + k + 2) = lp1;
}
// weights: [hi | lo | hi]
__global__ void conv_wt(const float* __restrict__ in, __nv_bfloat16* __restrict__ out,
                        int Nr, int K) {
    long long idx = (long long)blockIdx.x * 256 + threadIdx.x;
    long long tot = (long long)Nr * (K / 4);
    if (idx >= tot) return;
    int n = (int)(idx / (K / 4)), k = (int)(idx % (K / 4)) * 4;
    float4 v = *(const float4*)(in + (size_t)n * K + k);
    __nv_bfloat16 h0 = __float2bfloat16(v.x), h1 = __float2bfloat16(v.y);
    __nv_bfloat16 h2 = __float2bfloat16(v.z), h3 = __float2bfloat16(v.w);
    __nv_bfloat162 hp0 = __nv_bfloat162(h0, h1), hp1 = __nv_bfloat162(h2, h3);
    __nv_bfloat162 lp0 = __nv_bfloat162(__float2bfloat16(v.x - __bfloat162float(h0)),
                                        __float2bfloat16(v.y - __bfloat162float(h1)));
    __nv_bfloat162 lp1 = __nv_bfloat162(__float2bfloat16(v.z - __bfloat162float(h2)),
                                        __float2bfloat16(v.w - __bfloat162float(h3)));
    __nv_bfloat16* row = out + (size_t)n * 3 * K;
    *(__nv_bfloat162*)(row + k) = hp0;           *(__nv_bfloat162*)(row + k + 2) = hp1;
    *(__nv_bfloat162*)(row + K + k) = lp0;       *(__nv_bfloat162*)(row + K + k + 2) = lp1;
    *(__nv_bfloat162*)(row + 2 * K + k) = hp0;   *(__nv_bfloat162*)(row + 2 * K + k + 2) = hp1;
}

// ================= mma.sync bf16 NT GEMM =================
// C[M,N] = epi(Abf[M,Kp] * Bbf[N,Kp]^T).  M%128==0, N%BN==0, Kp%64==0.
// 256 threads, 8 warps 4(m) x 2(n). Warp tile 32 x BN/2.
template<int BN, bool GELU, bool RES>
__global__ void __launch_bounds__(256, 2)
gemm_mma(const __nv_bfloat16* __restrict__ A, const __nv_bfloat16* __restrict__ Bw,
         const float* __restrict__ bias, const float* __restrict__ res,
         float* __restrict__ C, int M, int N, int Kp) {
    constexpr int A_BYTES = 128 * 128;
    constexpr int B_BYTES = BN * 128;
    constexpr int STAGE = A_BYTES + B_BYTES;
    constexpr int NSTG = 3;
    constexpr int WN = BN / 2;
    constexpr int MF = 2;
    constexpr int NF = WN / 8;

    extern __shared__ char smraw[];
    char* sm = (char*)(((uintptr_t)smraw + 1023) & ~(uintptr_t)1023);
    uint32_t smb = smem_u32(sm);

    int tid = threadIdx.x, wid = tid >> 5, lane = tid & 31;
    int wm = wid & 3, wn = wid >> 2;
    int bm = blockIdx.y * 128, bn = blockIdx.x * BN;
    const __nv_bfloat16* Ab = A + (size_t)bm * Kp;
    const __nv_bfloat16* Bb = Bw + (size_t)bn * Kp;

    const int nk = Kp >> 6;

    auto load_tile = [&](int kt, int s) {
        int k0 = kt << 6;
        uint32_t sa = smb + s * STAGE;
        #pragma unroll
        for (int i = 0; i < (128 * 8) / 256; i++) {
            int idx = tid + i * 256;
            int r = idx >> 3, cb = (idx & 7) << 4;
            CP_ASYNC16(sa + swz((r << 7) | cb),
                       (const char*)(Ab + (size_t)r * Kp + k0) + cb);
        }
        uint32_t sb = sa + A_BYTES;
        #pragma unroll
        for (int i = 0; i < (BN * 8 + 255) / 256; i++) {
            int idx = tid + i * 256;
            if (BN * 8 % 256 == 0 || idx < BN * 8) {
                int r = idx >> 3, cb = (idx & 7) << 4;
                CP_ASYNC16(sb + swz((r << 7) | cb),
                           (const char*)(Bb + (size_t)r * Kp + k0) + cb);
            }
        }
    };

    float acc[MF][NF][4];
    #pragma unroll
    for (int i = 0; i < MF; i++)
        #pragma unroll
        for (int j = 0; j < NF; j++)
            #pragma unroll
            for (int e = 0; e < 4; e++) acc[i][j][e] = 0.0f;

    load_tile(0, 0); CP_COMMIT();
    if (nk > 1) load_tile(1, 1);
    CP_COMMIT();

    int a_mi = lane >> 3, a_r = lane & 7;
    int b_grp = lane >> 3, b_r = lane & 7;   // grp 0..3: (nf+grp/2, k+grp%2)

    for (int kt = 0; kt < nk; kt++) {
        CP_WAIT1();
        __syncthreads();
        int s = kt % NSTG;
        uint32_t sa = smb + s * STAGE;
        uint32_t sb = sa + A_BYTES;

        #pragma unroll
        for (int ks = 0; ks < 4; ks++) {
            uint32_t afr[MF][4];
            #pragma unroll
            for (int mf = 0; mf < MF; mf++) {
                int row = wm * 32 + mf * 16 + ((a_mi & 1) << 3) + a_r;
                int unit = ks * 2 + (a_mi >> 1);
                ldm_x4(afr[mf], sa + swz((row << 7) | (unit << 4)));
            }
            #pragma unroll
            for (int nfp = 0; nfp < NF / 2; nfp++) {
                uint32_t bfr[4];
                int row = wn * WN + (nfp * 2 + (b_grp >> 1)) * 8 + b_r;
                int unit = ks * 2 + (b_grp & 1);
                ldm_x4(bfr, sb + swz((row << 7) | (unit << 4)));
                #pragma unroll
                for (int mf = 0; mf < MF; mf++) {
                    mma_bf16(acc[mf][nfp * 2 + 0], afr[mf], bfr);
                    mma_bf16(acc[mf][nfp * 2 + 1], afr[mf], bfr + 2);
                }
            }
        }
        __syncthreads();
        if (kt + 2 < nk) load_tile(kt + 2, (kt + 2) % NSTG);
        CP_COMMIT();
    }

    int cr = lane >> 2, cc2 = (lane & 3) << 1;
    #pragma unroll
    for (int mf = 0; mf < MF; mf++) {
        #pragma unroll
        for (int half = 0; half < 2; half++) {
            int gm = bm + wm * 32 + mf * 16 + cr + half * 8;
            #pragma unroll
            for (int nf = 0; nf < NF; nf++) {
                int gn = bn + wn * WN + nf * 8 + cc2;
                float v0 = acc[mf][nf][half * 2 + 0];
                float v1 = acc[mf][nf][half * 2 + 1];
                if (bias) { v0 += __ldg(&bias[gn]); v1 += __ldg(&bias[gn + 1]); }
                if (GELU) { v0 = gelu_f(v0); v1 = gelu_f(v1); }
                if (RES) {
                    float2 rv = *(const float2*)(res + (size_t)gm * N + gn);
                    v0 += rv.x; v1 += rv.y;
                }
                *(float2*)(C + (size_t)gm * N + gn) = make_float2(v0, v1);
            }
        }
    }
}

// ---------------- LayerNorm D=768 ----------------
__global__ void ln768_kernel(const float* __restrict__ x, const float* __restrict__ g,
                             const float* __restrict__ b, float* __restrict__ out) {
    int row = blockIdx.x;
    const float* p = x + (size_t)row * CC;
    float* o = out + (size_t)row * CC;
    int tid = threadIdx.x;
    float v0 = p[tid], v1 = p[tid + 256], v2 = p[tid + 512];
    float s = v0 + v1 + v2;
    float sq = v0 * v0 + v1 * v1 + v2 * v2;
    __shared__ float rs[256], rq[256];
    rs[tid] = s; rq[tid] = sq; __syncthreads();
    for (int st = 128; st > 0; st >>= 1) {
        if (tid < st) { rs[tid] += rs[tid + st]; rq[tid] += rq[tid + st]; }
        __syncthreads();
    }
    float mean = rs[0] * (1.0f / CC);
    float var  = rq[0] * (1.0f / CC) - mean * mean;
    float inv = rsqrtf(var + 1e-5f);
    o[tid]       = (v0 - mean) * inv * g[tid]       + b[tid];
    o[tid + 256] = (v1 - mean) * inv * g[tid + 256] + b[tid + 256];
    o[tid + 512] = (v2 - mean) * inv * g[tid + 512] + b[tid + 512];
}

// ---------------- LayerNorm D=32 ----------------
__global__ void ln32_kernel(const float* __restrict__ x, const float* __restrict__ g,
                            const float* __restrict__ b, float* __restrict__ out) {
    int row = blockIdx.x * 8 + threadIdx.x / 32;
    int lane = threadIdx.x & 31;
    float v = x[(size_t)row * OUTC + lane];
    float s = v, sq = v * v;
    #pragma unroll
    for (int o = 16; o > 0; o >>= 1) {
        s  += __shfl_xor_sync(0xffffffff, s, o);
        sq += __shfl_xor_sync(0xffffffff, sq, o);
    }
    float mean = s * (1.0f / OUTC);
    float var  = sq * (1.0f / OUTC) - mean * mean;
    float inv = rsqrtf(var + 1e-5f);
    out[(size_t)row * OUTC + lane] = (v - mean) * inv * g[lane] + b[lane];
}

// ---------------- fp32 SIMT GEMM (small channel GEMMs) ----------------
template<int BM, int BN, int BK, int TM, int TN, bool GELU, bool RES>
__global__ void gemm_nt(const float* __restrict__ A, const float* __restrict__ Bw,
                        const float* __restrict__ bias, const float* __restrict__ res,
                        float* __restrict__ C, int M, int N, int K) {
    constexpr int THREADS = (BM / TM) * (BN / TN);
    __shared__ float As[BK][BM];
    __shared__ float Bs[BK][BN];
    int tid = threadIdx.x;
    int bm = blockIdx.y * BM, bn = blockIdx.x * BN;
    int tx = tid % (BN / TN), ty = tid / (BN / TN);
    float acc[TM][TN];
    #pragma unroll
    for (int i = 0; i < TM; i++)
        #pragma unroll
        for (int j = 0; j < TN; j++) acc[i][j] = 0.0f;
    constexpr int A4 = BM * BK / 4;
    constexpr int B4 = BN * BK / 4;
    for (int k0 = 0; k0 < K; k0 += BK) {
        #pragma unroll
        for (int i = tid; i < A4; i += THREADS) {
            int row = i / (BK / 4);
            int kk  = (i % (BK / 4)) * 4;
            float4 v = make_float4(0.f, 0.f, 0.f, 0.f);
            if (k0 + kk < K) v = *(const float4*)(A + (size_t)(bm + row) * K + k0 + kk);
            As[kk + 0][row] = v.x; As[kk + 1][row] = v.y;
            As[kk + 2][row] = v.z; As[kk + 3][row] = v.w;
        }
        #pragma unroll
        for (int i = tid; i < B4; i += THREADS) {
            int row = i / (BK / 4);
            int kk  = (i % (BK / 4)) * 4;
            float4 v = make_float4(0.f, 0.f, 0.f, 0.f);
            if (bn + row < N && k0 + kk < K)
                v = *(const float4*)(Bw + (size_t)(bn + row) * K + k0 + kk);
            Bs[kk + 0][row] = v.x; Bs[kk + 1][row] = v.y;
            Bs[kk + 2][row] = v.z; Bs[kk + 3][row] = v.w;
        }
        __syncthreads();
        #pragma unroll
        for (int kk = 0; kk < BK; kk++) {
            float a[TM], bv[TN];
            #pragma unroll
            for (int i = 0; i < TM; i++) a[i] = As[kk][ty * TM + i];
            #pragma unroll
            for (int j = 0; j < TN; j++) bv[j] = Bs[kk][tx * TN + j];
            #pragma unroll
            for (int i = 0; i < TM; i++)
                #pragma unroll
                for (int j = 0; j < TN; j++) acc[i][j] += a[i] * bv[j];
        }
        __syncthreads();
    }
    #pragma unroll
    for (int i = 0; i < TM; i++) {
        int gm = bm + ty * TM + i;
        #pragma unroll
        for (int j = 0; j < TN; j++) {
            int gn = bn + tx * TN + j;
            if (gn < N) {
                float v = acc[i][j];
                if (bias) v += bias[gn];
                if (GELU) v = gelu_f(v);
                if (RES) v += res[(size_t)gm * N + gn];
                C[(size_t)gm * N + gn] = v;
            }
        }
    }
}

// ---------------- Attention scores ----------------
__global__ void attn_qk_kernel(const float* __restrict__ qkv, float* __restrict__ S) {
    int bh = blockIdx.z;
    int b = bh / HH, h = bh % HH;
    int q0 = blockIdx.y * 64, k0 = blockIdx.x * 64;
    __shared__ float Qs[64][64];
    __shared__ float Ks[64][64];
    int tid = threadIdx.x;
    for (int i = tid; i < 1024; i += 256) {
        int r = i / 16, d4 = (i % 16) * 4;
        float4 v = make_float4(0.f, 0.f, 0.f, 0.f);
        if (q0 + r < NN)
            v = *(const float4*)(qkv + (size_t)(b * NN + q0 + r) * (3 * CC) + h * HD + d4);
        Qs[d4 + 0][r] = v.x; Qs[d4 + 1][r] = v.y; Qs[d4 + 2][r] = v.z; Qs[d4 + 3][r] = v.w;
        float4 w = make_float4(0.f, 0.f, 0.f, 0.f);
        if (k0 + r < NN)
            w = *(const float4*)(qkv + (size_t)(b * NN + k0 + r) * (3 * CC) + CC + h * HD + d4);
        Ks[d4 + 0][r] = w.x; Ks[d4 + 1][r] = w.y; Ks[d4 + 2][r] = w.z; Ks[d4 + 3][r] = w.w;
    }
    __syncthreads();
    int tx = tid % 16, ty = tid / 16;
    float acc[4][4] = {};
    #pragma unroll
    for (int d = 0; d < 64; d++) {
        float a[4], bb[4];
        #pragma unroll
        for (int i = 0; i < 4; i++) a[i] = Qs[d][ty * 4 + i];
        #pragma unroll
        for (int j = 0; j < 4; j++) bb[j] = Ks[d][tx * 4 + j];
        #pragma unroll
        for (int i = 0; i < 4; i++)
            #pragma unroll
            for (int j = 0; j < 4; j++) acc[i][j] += a[i] * bb[j];
    }
    #pragma unroll
    for (int i = 0; i < 4; i++) {
        int q = q0 + ty * 4 + i;
        #pragma unroll
        for (int j = 0; j < 4; j++) {
            int k = k0 + tx * 4 + j;
            if (q < NN && k < NN)
                S[((size_t)bh * NN + q) * NN + k] = acc[i][j] * 0.125f;
        }
    }
}

// ---------------- warp-per-row softmax over 197 ----------------
__global__ void softmax197_warp(float* __restrict__ S) {
    int row = blockIdx.x * 8 + (threadIdx.x >> 5);
    int lane = threadIdx.x & 31;
    float* p = S + (size_t)row * NN;
    float v[7];
    float mx = -INFINITY;
    #pragma unroll
    for (int j = 0; j < 7; j++) {
        int idx = lane + 32 * j;
        v[j] = (idx < NN) ? p[idx] : -INFINITY;
        mx = fmaxf(mx, v[j]);
    }
    #pragma unroll
    for (int o = 16; o > 0; o >>= 1) mx = fmaxf(mx, __shfl_xor_sync(0xffffffff, mx, o));
    float sum = 0.0f;
    #pragma unroll
    for (int j = 0; j < 7; j++) { v[j] = __expf(v[j] - mx); sum += (lane + 32 * j < NN) ? v[j] : 0.0f; }
    #pragma unroll
    for (int o = 16; o > 0; o >>= 1) sum += __shfl_xor_sync(0xffffffff, sum, o);
    float inv = 1.0f / sum;
    #pragma unroll
    for (int j = 0; j < 7; j++) {
        int idx = lane + 32 * j;
        if (idx < NN) p[idx] = v[j] * inv;
    }
}

// ---------------- O = P @ V ----------------
__global__ void attn_av_kernel(const float* __restrict__ P, const float* __restrict__ qkv,
                               float* __restrict__ O) {
    int bh = blockIdx.y;
    int b = bh / HH, h = bh % HH;
    int q0 = blockIdx.x * 64;
    __shared__ float As[32][64];
    __shared__ float Vs[32][64];
    int tid = threadIdx.x, tx = tid % 16, ty = tid / 16;
    float acc[4][4] = {};
    for (int kt = 0; kt < NN; kt += 32) {
        for (int i = tid; i < 2048; i += 256) {
            int qi = i / 32, kk = i % 32;
            float v = 0.0f;
            if (q0 + qi < NN && kt + kk < NN)
                v = P[((size_t)bh * NN + q0 + qi) * NN + kt + kk];
            As[kk][qi] = v;
        }
        for (int i = tid; i < 512; i += 256) {
            int kk = i / 16, d4 = (i % 16) * 4;
            float4 v = make_float4(0.f, 0.f, 0.f, 0.f);
            if (kt + kk < NN)
                v = *(const float4*)(qkv + (size_t)(b * NN + kt + kk) * (3 * CC) + 2 * CC + h * HD + d4);
            *(float4*)&Vs[kk][d4] = v;
        }
        __syncthreads();
        #pragma unroll
        for (int kk = 0; kk < 32; kk++) {
            float a[4], bv[4];
            #pragma unroll
            for (int i = 0; i < 4; i++) a[i] = As[kk][ty * 4 + i];
            #pragma unroll
            for (int j = 0; j < 4; j++) bv[j] = Vs[kk][tx * 4 + j];
            #pragma unroll
            for (int i = 0; i < 4; i++)
                #pragma unroll
                for (int j = 0; j < 4; j++) acc[i][j] += a[i] * bv[j];
        }
        __syncthreads();
    }
    #pragma unroll
    for (int i = 0; i < 4; i++) {
        int q = q0 + ty * 4 + i;
        if (q < NN) {
            #pragma unroll
            for (int j = 0; j < 4; j++)
                O[((size_t)(b * NN + q)) * CC + h * HD + tx * 4 + j] = acc[i][j];
        }
    }
}

// ---------------- t[b,c,s] = ln3[b, 1+s, c] ----------------
__global__ void make_t_kernel(const float* __restrict__ ln3, float* __restrict__ t) {
    int idx = blockIdx.x * 256 + threadIdx.x;
    if (idx >= BB * OUTC * CNN) return;
    int s = idx % CNN;
    int c = (idx / CNN) % OUTC;
    int b = idx / (CNN * OUTC);
    t[idx] = ln3[((size_t)(b * NN + 1 + s)) * OUTC + c];
}

// ---------------- tiny channel attention ----------------
__global__ void chattn_kernel(const float* __restrict__ cqkv, float* __restrict__ co) {
    int b = blockIdx.x / CHH, h = blockIdx.x % CHH;
    int tid = threadIdx.x;
    __shared__ float Q[OUTC][CHD], Kk[OUTC][CHD], V[OUTC][CHD], S[OUTC][OUTC + 1];
    const float* base = cqkv + (size_t)b * OUTC * (3 * CNN);
    for (int i = tid; i < OUTC * CHD; i += 256) {
        int r = i / CHD, d = i % CHD;
        Q[r][d]  = base[r * (3 * CNN) + h * CHD + d];
        Kk[r][d] = base[r * (3 * CNN) + CNN + h * CHD + d];
        V[r][d]  = base[r * (3 * CNN) + 2 * CNN + h * CHD + d];
    }
    __syncthreads();
    const float sc = rsqrtf((float)CHD);
    for (int i = tid; i < OUTC * OUTC; i += 256) {
        int qi = i / OUTC, kj = i % OUTC;
        float s = 0.0f;
        #pragma unroll
        for (int d = 0; d < CHD; d++) s += Q[qi][d] * Kk[kj][d];
        S[qi][kj] = s * sc;
    }
    __syncthreads();
    if (tid < OUTC) {
        float mx = -INFINITY;
        #pragma unroll
        for (int j = 0; j < OUTC; j++) mx = fmaxf(mx, S[tid][j]);
        float sum = 0.0f;
        #pragma unroll
        for (int j = 0; j < OUTC; j++) { float e = __expf(S[tid][j] - mx); S[tid][j] = e; sum += e; }
        float inv = 1.0f / sum;
        #pragma unroll
        for (int j = 0; j < OUTC; j++) S[tid][j] *= inv;
    }
    __syncthreads();
    for (int i = tid; i < OUTC * CHD; i += 256) {
        int qi = i / CHD, d = i % CHD;
        float s = 0.0f;
        #pragma unroll
        for (int kk = 0; kk < OUTC; kk++) s += S[qi][kk] * V[kk][d];
        co[((size_t)(b * OUTC + qi)) * CNN + h * CHD + d] = s;
    }
}

// ---------------- x32 += concat([ln3 cls, co2^T]) ----------------
__global__ void concat_add_kernel(const float* __restrict__ ln3, const float* __restrict__ co2,
                                  float* __restrict__ x32) {
    int idx = blockIdx.x * 256 + threadIdx.x;
    if (idx >= MROWS * OUTC) return;
    int c = idx % OUTC;
    int n = (idx / OUTC) % NN;
    int b = idx / (OUTC * NN);
    float add;
    if (n == 0) add = ln3[((size_t)b * NN) * OUTC + c];
    else        add = co2[((size_t)(b * OUTC + c)) * CNN + (n - 1)];
    x32[idx] += add;
}

// ---------------- launch ----------------
static inline int cdiv(long long a, int b) { return (int)((a + b - 1) / b); }

extern "C" void kernel_launch(void* const* d_in, const int* in_sizes, int n_in,
                              void* d_out, int out_size) {
    const float* x      = (const float*)d_in[0];
    const float* g1     = (const float*)d_in[1];
    const float* b1     = (const float*)d_in[2];
    const float* w_qkv  = (const float*)d_in[3];
    const float* w_proj = (const float*)d_in[4];
    const float* b_proj = (const float*)d_in[5];
    const float* g2     = (const float*)d_in[6];
    const float* b2     = (const float*)d_in[7];
    const float* w_fc1  = (const float*)d_in[8];
    const float* b_fc1  = (const float*)d_in[9];
    const float* w_fc2  = (const float*)d_in[10];
    const float* b_fc2  = (const float*)d_in[11];
    const float* g3     = (const float*)d_in[12];
    const float* b3     = (const float*)d_in[13];
    const float* w_cqkv = (const float*)d_in[14];
    const float* w_cproj= (const float*)d_in[15];
    const float* b_cproj= (const float*)d_in[16];
    const float* g4     = (const float*)d_in[17];
    const float* b4     = (const float*)d_in[18];
    const float* w_cfc1 = (const float*)d_in[19];
    const float* b_cfc1 = (const float*)d_in[20];
    const float* w_cfc2 = (const float*)d_in[21];
    const float* b_cfc2 = (const float*)d_in[22];
    float* out = (float*)d_out;

    float *p_ln, *p_qkv, *p_attn, *p_o, *p_x, *p_mlp, *p_x32, *p_ln32, *p_t, *p_cqkv, *p_co, *p_co2, *p_cmlp;
    __nv_bfloat16 *p_abf, *p_wbf;
    cudaGetSymbolAddress((void**)&p_ln,   g_ln);
    cudaGetSymbolAddress((void**)&p_qkv,  g_qkv);
    cudaGetSymbolAddress((void**)&p_attn, g_attn);
    cudaGetSymbolAddress((void**)&p_o,    g_o);
    cudaGetSymbolAddress((void**)&p_x,    g_x);
    cudaGetSymbolAddress((void**)&p_mlp,  g_mlp);
    cudaGetSymbolAddress((void**)&p_x32,  g_x32);
    cudaGetSymbolAddress((void**)&p_ln32, g_ln32);
    cudaGetSymbolAddress((void**)&p_t,    g_t);
    cudaGetSymbolAddress((void**)&p_cqkv, g_cqkv);
    cudaGetSymbolAddress((void**)&p_co,   g_co);
    cudaGetSymbolAddress((void**)&p_co2,  g_co2);
    cudaGetSymbolAddress((void**)&p_cmlp, g_cmlp);
    cudaGetSymbolAddress((void**)&p_abf,  g_abf);
    cudaGetSymbolAddress((void**)&p_wbf,  g_wbf);

    const int SM128 = 3 * (128 * 128 + 128 * 128) + 1024;   // 99328
    const int SM32  = 3 * (128 * 128 + 32 * 128) + 1024;    // 62464
    cudaFuncSetAttribute(gemm_mma<128, false, false>, cudaFuncAttributeMaxDynamicSharedMemorySize, SM128);
    cudaFuncSetAttribute(gemm_mma<128, false, true >, cudaFuncAttributeMaxDynamicSharedMemorySize, SM128);
    cudaFuncSetAttribute(gemm_mma<128, true,  false>, cudaFuncAttributeMaxDynamicSharedMemorySize, SM128);
    cudaFuncSetAttribute(gemm_mma<32,  false, false>, cudaFuncAttributeMaxDynamicSharedMemorySize, SM32);
    cudaFuncSetAttribute(gemm_mma<32,  false, true >, cudaFuncAttributeMaxDynamicSharedMemorySize, SM32);

    const int M = MROWS;  // 25216 = 128*197
    const int MB = M / 128;

    // 1. LN1
    ln768_kernel<<<M, 256>>>(x, g1, b1, p_ln);
    // 2. qkv = ln1 @ w_qkv^T  (bf16x3)
    conv_act<<<cdiv((long long)M * CC / 4, 256), 256>>>(p_ln, p_abf, M, CC);
    conv_wt <<<cdiv((long long)3 * CC * CC / 4, 256), 256>>>(w_qkv, p_wbf, 3 * CC, CC);
    gemm_mma<128, false, false><<<dim3(18, MB), 256, SM128>>>(p_abf, p_wbf, nullptr, nullptr, p_qkv, M, 3 * CC, 3 * CC);
    // 3-5. attention
    attn_qk_kernel<<<dim3(4, 4, BB * HH), 256>>>(p_qkv, p_attn);
    softmax197_warp<<<BB * HH * NN / 8, 256>>>(p_attn);
    attn_av_kernel<<<dim3(4, BB * HH), 256>>>(p_attn, p_qkv, p_o);
    // 6. x = x_in + O @ w_proj^T + b_proj
    conv_act<<<cdiv((long long)M * CC / 4, 256), 256>>>(p_o, p_abf, M, CC);
    conv_wt <<<cdiv((long long)CC * CC / 4, 256), 256>>>(w_proj, p_wbf, CC, CC);
    gemm_mma<128, false, true><<<dim3(6, MB), 256, SM128>>>(p_abf, p_wbf, b_proj, x, p_x, M, CC, 3 * CC);
    // 7. LN2
    ln768_kernel<<<M, 256>>>(p_x, g2, b2, p_ln);
    // 8. hidden = gelu(ln2 @ w_fc1^T + b_fc1)
    conv_act<<<cdiv((long long)M * CC / 4, 256), 256>>>(p_ln, p_abf, M, CC);
    conv_wt <<<cdiv((long long)MLPH * CC / 4, 256), 256>>>(w_fc1, p_wbf, MLPH, CC);
    gemm_mma<128, true, false><<<dim3(24, MB), 256, SM128>>>(p_abf, p_wbf, b_fc1, nullptr, p_mlp, M, MLPH, 3 * CC);
    // 9. x32 = hidden @ w_fc2^T + b_fc2
    conv_act<<<cdiv((long long)M * MLPH / 4, 256), 256>>>(p_mlp, p_abf, M, MLPH);
    conv_wt <<<cdiv((long long)OUTC * MLPH / 4, 256), 256>>>(w_fc2, p_wbf, OUTC, MLPH);
    gemm_mma<32, false, false><<<dim3(1, MB), 256, SM32>>>(p_abf, p_wbf, b_fc2, nullptr, p_x32, M, OUTC, 3 * MLPH);
    // 10. LN3
    ln32_kernel<<<M / 8, 256>>>(p_x32, g3, b3, p_ln32);
    // 11. build t
    make_t_kernel<<<(BB * OUTC * CNN + 255) / 256, 256>>>(p_ln32, p_t);
    // 12. cqkv = t @ w_cqkv^T
    gemm_nt<128, 128, 16, 8, 8, false, false><<<dim3(5, CMROWS / 128), 256>>>(p_t, w_cqkv, nullptr, nullptr, p_cqkv, CMROWS, 3 * CNN, CNN);
    // 13. channel attention
    chattn_kernel<<<BB * CHH, 256>>>(p_cqkv, p_co);
    // 14. co2 = co @ w_cproj^T + b_cproj
    gemm_nt<128, 128, 16, 8, 8, false, false><<<dim3(2, CMROWS / 128), 256>>>(p_co, w_cproj, b_cproj, nullptr, p_co2, CMROWS, CNN, CNN);
    // 15. x32 += concat
    concat_add_kernel<<<(M * OUTC + 255) / 256, 256>>>(p_ln32, p_co2, p_x32);
    // 16. LN4
    ln32_kernel<<<M / 8, 256>>>(p_x32, g4, b4, p_ln32);
    // 17. cmlp = gelu(ln4 @ w_cfc1^T + b_cfc1)
    gemm_nt<128, 128, 16, 8, 8, true, false><<<dim3(1, MB), 256>>>(p_ln32, w_cfc1, b_cfc1, nullptr, p_cmlp, M, CMLPH, OUTC);
    // 18. out = x32 + cmlp @ w_cfc2^T + b_cfc2  (bf16x3)
    conv_act<<<cdiv((long long)M * CMLPH / 4, 256), 256>>>(p_cmlp, p_abf, M, CMLPH);
    conv_wt <<<cdiv((long long)OUTC * CMLPH / 4, 256), 256>>>(w_cfc2, p_wbf, OUTC, CMLPH);
    gemm_mma<32, false, true><<<dim3(1, MB), 256, SM32>>>(p_abf, p_wbf, b_cfc2, p_x32, out, M, OUTC, 3 * CMLPH);
}

// round 6
// speedup vs baseline: 3.2340x; 1.2913x over previous
#include <cuda_runtime.h>
#include <cuda_bf16.h>
#include <math.h>
#include <stdint.h>
#include <stddef.h>

#define BB   128
#define NN   197
#define CC   768
#define HH   12
#define HD   64
#define OUTC 32
#define CHH  14
#define CHD  14
#define CNN  196
#define MLPH 3072
#define CMLPH 128
#define MROWS (BB*NN)          // 25216
#define CMROWS (BB*OUTC)       // 4096
#define NBH   (BB*HH)          // 1536

// ---------------- scratch ----------------
__device__ float g_qkv [MROWS*3*CC];
__device__ float g_attn[(size_t)NBH*NN*NN];
__device__ float g_x   [MROWS*CC];
__device__ float g_x32 [MROWS*OUTC];
__device__ float g_ln32[MROWS*OUTC];
__device__ float g_t   [BB*OUTC*CNN];
__device__ float g_cqkv[BB*OUTC*3*CNN];
__device__ float g_co  [BB*OUTC*CNN];
__device__ float g_co2 [BB*OUTC*CNN];
__device__ float g_cmlp[MROWS*CMLPH];
__device__ __nv_bfloat16 g_abf [(size_t)MROWS*3*CC];    // K'=2304 activations
__device__ __nv_bfloat16 g_abf2[(size_t)MROWS*3*MLPH];  // K'=9216 mlp hidden
__device__ __nv_bfloat16 g_wbf [(size_t)MLPH*3*CC];     // weights
__device__ __nv_bfloat16 g_qs  [(size_t)NBH*4*3*4096];  // Q' slabs
__device__ __nv_bfloat16 g_ks  [(size_t)NBH*4*3*4096];  // K' slabs
__device__ __nv_bfloat16 g_vt  [(size_t)NBH*4*3*4096];  // V^T slabs

__device__ __forceinline__ float gelu_f(float x) {
    return 0.5f * x * (1.0f + erff(x * 0.70710678118654752440f));
}

// ================= PTX helpers =================
__device__ __forceinline__ uint32_t smem_u32(const void* p) {
    uint32_t a;
    asm("{ .reg .u64 t; cvta.to.shared.u64 t, %1; cvt.u32.u64 %0, t; }" : "=r"(a) : "l"(p));
    return a;
}
#define CP_ASYNC16(d, s)    asm volatile("cp.async.cg.shared.global [%0], [%1], 16;" :: "r"(d), "l"(s))
#define CP_COMMIT()         asm volatile("cp.async.commit_group;" ::: "memory")
#define CP_WAIT1()          asm volatile("cp.async.wait_group 1;" ::: "memory")
#define CP_WAIT0()          asm volatile("cp.async.wait_group 0;" ::: "memory")

__device__ __forceinline__ void ldm_x4(uint32_t* r, uint32_t addr) {
    asm volatile("ldmatrix.sync.aligned.m8n8.x4.shared.b16 {%0,%1,%2,%3}, [%4];"
        : "=r"(r[0]), "=r"(r[1]), "=r"(r[2]), "=r"(r[3]) : "r"(addr));
}
__device__ __forceinline__ void mma_bf16(float* c, const uint32_t* a, const uint32_t* b) {
    asm volatile("mma.sync.aligned.m16n8k16.row.col.f32.bf16.bf16.f32 "
        "{%0,%1,%2,%3}, {%4,%5,%6,%7}, {%8,%9}, {%0,%1,%2,%3};"
        : "+f"(c[0]), "+f"(c[1]), "+f"(c[2]), "+f"(c[3])
        : "r"(a[0]), "r"(a[1]), "r"(a[2]), "r"(a[3]), "r"(b[0]), "r"(b[1]));
}
__device__ __forceinline__ uint32_t swz(uint32_t off) { return off ^ ((off >> 3) & 0x70); }
__device__ __forceinline__ void split2(float a, float b, __nv_bfloat162& hp, __nv_bfloat162& lp) {
    __nv_bfloat16 h0 = __float2bfloat16(a), h1 = __float2bfloat16(b);
    hp = __nv_bfloat162(h0, h1);
    lp = __nv_bfloat162(__float2bfloat16(a - __bfloat162float(h0)),
                        __float2bfloat16(b - __bfloat162float(h1)));
}

// ================= conversions =================
// generic activation split [hi|hi|lo] (still used for cfc2 input)
__global__ void conv_act(const float* __restrict__ in, __nv_bfloat16* __restrict__ out,
                         int Mr, int K) {
    long long idx = (long long)blockIdx.x * 256 + threadIdx.x;
    long long tot = (long long)Mr * (K / 4);
    if (idx >= tot) return;
    int m = (int)(idx / (K / 4)), k = (int)(idx % (K / 4)) * 4;
    float4 v = *(const float4*)(in + (size_t)m * K + k);
    __nv_bfloat162 hp0, lp0, hp1, lp1;
    split2(v.x, v.y, hp0, lp0); split2(v.z, v.w, hp1, lp1);
    __nv_bfloat16* row = out + (size_t)m * 3 * K;
    *(__nv_bfloat162*)(row + k) = hp0;           *(__nv_bfloat162*)(row + k + 2) = hp1;
    *(__nv_bfloat162*)(row + K + k) = hp0;       *(__nv_bfloat162*)(row + K + k + 2) = hp1;
    *(__nv_bfloat162*)(row + 2 * K + k) = lp0;   *(__nv_bfloat162*)(row + 2 * K + k + 2) = lp1;
}
// weights: [hi | lo | hi]
__global__ void conv_wt(const float* __restrict__ in, __nv_bfloat16* __restrict__ out,
                        int Nr, int K) {
    long long idx = (long long)blockIdx.x * 256 + threadIdx.x;
    long long tot = (long long)Nr * (K / 4);
    if (idx >= tot) return;
    int n = (int)(idx / (K / 4)), k = (int)(idx % (K / 4)) * 4;
    float4 v = *(const float4*)(in + (size_t)n * K + k);
    __nv_bfloat162 hp0, lp0, hp1, lp1;
    split2(v.x, v.y, hp0, lp0); split2(v.z, v.w, hp1, lp1);
    __nv_bfloat16* row = out + (size_t)n * 3 * K;
    *(__nv_bfloat162*)(row + k) = hp0;           *(__nv_bfloat162*)(row + k + 2) = hp1;
    *(__nv_bfloat162*)(row + K + k) = lp0;       *(__nv_bfloat162*)(row + K + k + 2) = lp1;
    *(__nv_bfloat162*)(row + 2 * K + k) = hp0;   *(__nv_bfloat162*)(row + 2 * K + k + 2) = hp1;
}
// q,k slabs from g_qkv: [bh][qtile][slab(3)][64 rows][64 bf16]
__global__ void conv_qk(const float* __restrict__ qkv, __nv_bfloat16* __restrict__ Qs,
                        __nv_bfloat16* __restrict__ Ks) {
    int idx = blockIdx.x * 256 + threadIdx.x;    // NBH*197*32
    if (idx >= NBH * 197 * 32) return;
    int d2 = (idx & 31) * 2;
    int n  = (idx >> 5) % 197;
    int bh = idx / (32 * 197);
    int b = bh / HH, h = bh % HH;
    const float* src = qkv + (size_t)(b * NN + n) * (3 * CC) + h * HD + d2;
    float2 q = *(const float2*)src;
    float2 k = *(const float2*)(src + CC);
    __nv_bfloat162 qh, ql, kh, kl;
    split2(q.x, q.y, qh, ql); split2(k.x, k.y, kh, kl);
    int qt = n >> 6, r = n & 63;
    size_t base = ((size_t)(bh * 4 + qt) * 3) * 4096 + r * 64 + d2;
    *(__nv_bfloat162*)(Qs + base)        = qh;
    *(__nv_bfloat162*)(Qs + base + 4096) = qh;
    *(__nv_bfloat162*)(Qs + base + 8192) = ql;
    *(__nv_bfloat162*)(Ks + base)        = kh;
    *(__nv_bfloat162*)(Ks + base + 4096) = kl;
    *(__nv_bfloat162*)(Ks + base + 8192) = kh;
}
// v transpose+split: [bh][ktile][slab(3)][64 rows(d)][64 bf16(kk)], zero-padded keys
__global__ void conv_vt(const float* __restrict__ qkv, __nv_bfloat16* __restrict__ Vt) {
    int ct = blockIdx.x;          // bh*4 + kt
    int bh = ct >> 2, kt = ct & 3;
    int b = bh / HH, h = bh % HH;
    __shared__ float t[64][65];
    int tid = threadIdx.x;
    for (int i = tid; i < 4096; i += 256) {
        int kk = i >> 6, d = i & 63;
        int k = kt * 64 + kk;
        t[kk][d] = (k < NN) ? qkv[(size_t)(b * NN + k) * (3 * CC) + 2 * CC + h * HD + d] : 0.f;
    }
    __syncthreads();
    __nv_bfloat16* dst = Vt + ((size_t)ct * 3) * 4096;
    for (int i = tid; i < 2048; i += 256) {
        int d = i >> 5, kk2 = (i & 31) << 1;
        __nv_bfloat162 hp, lp;
        split2(t[kk2][d], t[kk2 + 1][d], hp, lp);
        size_t base = (size_t)d * 64 + kk2;
        *(__nv_bfloat162*)(dst + base)        = hp;
        *(__nv_bfloat162*)(dst + base + 4096) = lp;
        *(__nv_bfloat162*)(dst + base + 8192) = hp;
    }
}

// ================= mma.sync bf16 NT GEMM =================
template<int BN, bool GELU, bool RES, bool X3>
__global__ void __launch_bounds__(256, 2)
gemm_mma(const __nv_bfloat16* __restrict__ A, const __nv_bfloat16* __restrict__ Bw,
         const float* __restrict__ bias, const float* __restrict__ res,
         float* __restrict__ C, __nv_bfloat16* __restrict__ Cx3, int M, int N, int Kp) {
    constexpr int A_BYTES = 128 * 128;
    constexpr int B_BYTES = BN * 128;
    constexpr int STAGE = A_BYTES + B_BYTES;
    constexpr int NSTG = 3;
    constexpr int WN = BN / 2;
    constexpr int MF = 2;
    constexpr int NF = WN / 8;

    extern __shared__ char smraw[];
    char* sm = (char*)(((uintptr_t)smraw + 1023) & ~(uintptr_t)1023);
    uint32_t smb = smem_u32(sm);

    int tid = threadIdx.x, wid = tid >> 5, lane = tid & 31;
    int wm = wid & 3, wn = wid >> 2;
    int bm = blockIdx.y * 128, bn = blockIdx.x * BN;
    const __nv_bfloat16* Ab = A + (size_t)bm * Kp;
    const __nv_bfloat16* Bb = Bw + (size_t)bn * Kp;
    const int nk = Kp >> 6;

    auto load_tile = [&](int kt, int s) {
        int k0 = kt << 6;
        uint32_t sa = smb + s * STAGE;
        #pragma unroll
        for (int i = 0; i < (128 * 8) / 256; i++) {
            int idx = tid + i * 256;
            int r = idx >> 3, cb = (idx & 7) << 4;
            CP_ASYNC16(sa + swz((r << 7) | cb), (const char*)(Ab + (size_t)r * Kp + k0) + cb);
        }
        uint32_t sb = sa + A_BYTES;
        #pragma unroll
        for (int i = 0; i < (BN * 8 + 255) / 256; i++) {
            int idx = tid + i * 256;
            if (BN * 8 % 256 == 0 || idx < BN * 8) {
                int r = idx >> 3, cb = (idx & 7) << 4;
                CP_ASYNC16(sb + swz((r << 7) | cb), (const char*)(Bb + (size_t)r * Kp + k0) + cb);
            }
        }
    };

    float acc[MF][NF][4];
    #pragma unroll
    for (int i = 0; i < MF; i++)
        #pragma unroll
        for (int j = 0; j < NF; j++)
            #pragma unroll
            for (int e = 0; e < 4; e++) acc[i][j][e] = 0.0f;

    load_tile(0, 0); CP_COMMIT();
    if (nk > 1) load_tile(1, 1);
    CP_COMMIT();

    int a_mi = lane >> 3, a_r = lane & 7;
    int b_grp = lane >> 3, b_r = lane & 7;

    for (int kt = 0; kt < nk; kt++) {
        CP_WAIT1();
        __syncthreads();
        int s = kt % NSTG;
        uint32_t sa = smb + s * STAGE;
        uint32_t sb = sa + A_BYTES;
        #pragma unroll
        for (int ks = 0; ks < 4; ks++) {
            uint32_t afr[MF][4];
            #pragma unroll
            for (int mf = 0; mf < MF; mf++) {
                int row = wm * 32 + mf * 16 + ((a_mi & 1) << 3) + a_r;
                ldm_x4(afr[mf], sa + swz((row << 7) | ((ks * 2 + (a_mi >> 1)) << 4)));
            }
            #pragma unroll
            for (int nfp = 0; nfp < NF / 2; nfp++) {
                uint32_t bfr[4];
                int row = wn * WN + (nfp * 2 + (b_grp >> 1)) * 8 + b_r;
                ldm_x4(bfr, sb + swz((row << 7) | ((ks * 2 + (b_grp & 1)) << 4)));
                #pragma unroll
                for (int mf = 0; mf < MF; mf++) {
                    mma_bf16(acc[mf][nfp * 2 + 0], afr[mf], bfr);
                    mma_bf16(acc[mf][nfp * 2 + 1], afr[mf], bfr + 2);
                }
            }
        }
        __syncthreads();
        if (kt + 2 < nk) load_tile(kt + 2, (kt + 2) % NSTG);
        CP_COMMIT();
    }

    int cr = lane >> 2, cc2 = (lane & 3) << 1;
    #pragma unroll
    for (int mf = 0; mf < MF; mf++) {
        #pragma unroll
        for (int half = 0; half < 2; half++) {
            int gm = bm + wm * 32 + mf * 16 + cr + half * 8;
            #pragma unroll
            for (int nf = 0; nf < NF; nf++) {
                int gn = bn + wn * WN + nf * 8 + cc2;
                float v0 = acc[mf][nf][half * 2 + 0];
                float v1 = acc[mf][nf][half * 2 + 1];
                if (bias) { v0 += __ldg(&bias[gn]); v1 += __ldg(&bias[gn + 1]); }
                if (GELU) { v0 = gelu_f(v0); v1 = gelu_f(v1); }
                if (X3) {
                    __nv_bfloat162 hp, lp;
                    split2(v0, v1, hp, lp);
                    __nv_bfloat16* row = Cx3 + (size_t)gm * (3 * N);
                    *(__nv_bfloat162*)(row + gn) = hp;
                    *(__nv_bfloat162*)(row + N + gn) = hp;
                    *(__nv_bfloat162*)(row + 2 * N + gn) = lp;
                } else {
                    if (RES) {
                        float2 rv = *(const float2*)(res + (size_t)gm * N + gn);
                        v0 += rv.x; v1 += rv.y;
                    }
                    *(float2*)(C + (size_t)gm * N + gn) = make_float2(v0, v1);
                }
            }
        }
    }
}

// ================= HMMA attention =================
// scores: one CTA per (ktile, qtile, bh); 128 threads
__global__ void __launch_bounds__(128)
attn_qk_mma(const __nv_bfloat16* __restrict__ Qs, const __nv_bfloat16* __restrict__ Ks,
            float* __restrict__ S) {
    __shared__ __align__(128) char sm[49152];
    char* smp = sm;
    uint32_t smb = smem_u32(sm);
    int kt = blockIdx.x, qt = blockIdx.y, bh = blockIdx.z;
    int tid = threadIdx.x, wid = tid >> 5, lane = tid & 31;
    const char* Qb = (const char*)(Qs + ((size_t)(bh * 4 + qt) * 3) * 4096);
    const char* Kb = (const char*)(Ks + ((size_t)(bh * 4 + kt) * 3) * 4096);
    for (int c = tid; c < 1536; c += 128) {
        int slab = c >> 9, rem = c & 511, row = rem >> 3, unit = rem & 7;
        uint32_t off = slab * 8192 + swz((row << 7) | (unit << 4));
        CP_ASYNC16(smb + off, Qb + (size_t)c * 16);
        CP_ASYNC16(smb + 24576 + off, Kb + (size_t)c * 16);
    }
    CP_COMMIT(); CP_WAIT0();
    __syncthreads();
    (void)smp;

    float acc[8][4];
    #pragma unroll
    for (int i = 0; i < 8; i++)
        #pragma unroll
        for (int e = 0; e < 4; e++) acc[i][e] = 0.f;
    int a_mi = lane >> 3, a_r = lane & 7, b_grp = lane >> 3, b_r = lane & 7;
    uint32_t smQ = smb, smK = smb + 24576;
    #pragma unroll
    for (int slab = 0; slab < 3; slab++) {
        #pragma unroll
        for (int ks = 0; ks < 4; ks++) {
            uint32_t afr[4];
            int arow = wid * 16 + ((a_mi & 1) << 3) + a_r;
            ldm_x4(afr, smQ + slab * 8192 + swz((arow << 7) | ((ks * 2 + (a_mi >> 1)) << 4)));
            #pragma unroll
            for (int nfp = 0; nfp < 4; nfp++) {
                uint32_t bfr[4];
                int brow = (nfp * 2 + (b_grp >> 1)) * 8 + b_r;
                ldm_x4(bfr, smK + slab * 8192 + swz((brow << 7) | ((ks * 2 + (b_grp & 1)) << 4)));
                mma_bf16(acc[nfp * 2 + 0], afr, bfr);
                mma_bf16(acc[nfp * 2 + 1], afr, bfr + 2);
            }
        }
    }
    int cr = lane >> 2, cc2 = (lane & 3) << 1;
    #pragma unroll
    for (int nf = 0; nf < 8; nf++) {
        #pragma unroll
        for (int half = 0; half < 2; half++) {
            int q = qt * 64 + wid * 16 + cr + half * 8;
            int k = kt * 64 + nf * 8 + cc2;
            if (q < NN) {
                float* dst = S + ((size_t)bh * NN + q) * NN + k;
                if (k < NN)     dst[0] = acc[nf][half * 2 + 0] * 0.125f;
                if (k + 1 < NN) dst[1] = acc[nf][half * 2 + 1] * 0.125f;
            }
        }
    }
}

// O = P@V, writes bf16x3 directly into proj's A buffer
__global__ void __launch_bounds__(128)
attn_av_mma(const float* __restrict__ P, const __nv_bfloat16* __restrict__ Vt,
            __nv_bfloat16* __restrict__ Ox3) {
    __shared__ __align__(128) char sm[49152];
    char* smp = sm;
    uint32_t smb = smem_u32(sm);
    int qt = blockIdx.x, bh = blockIdx.y;
    int b = bh / HH, h = bh % HH;
    int tid = threadIdx.x, wid = tid >> 5, lane = tid & 31;
    float acc[8][4];
    #pragma unroll
    for (int i = 0; i < 8; i++)
        #pragma unroll
        for (int e = 0; e < 4; e++) acc[i][e] = 0.f;
    int a_mi = lane >> 3, a_r = lane & 7, b_grp = lane >> 3, b_r = lane & 7;
    uint32_t smP = smb, smV = smb + 24576;

    for (int kt = 0; kt < 4; kt++) {
        const char* Vb = (const char*)(Vt + ((size_t)(bh * 4 + kt) * 3) * 4096);
        for (int c = tid; c < 1536; c += 128) {
            int slab = c >> 9, rem = c & 511, row = rem >> 3, unit = rem & 7;
            CP_ASYNC16(smV + slab * 8192 + swz((row << 7) | (unit << 4)), Vb + (size_t)c * 16);
        }
        CP_COMMIT();
        #pragma unroll
        for (int i = 0; i < 8; i++) {
            int lin = i * 128 + tid;
            int q = lin >> 4, k4 = (lin & 15) << 2;
            int qg = qt * 64 + q, kg = kt * 64 + k4;
            float p[4];
            #pragma unroll
            for (int e = 0; e < 4; e++)
                p[e] = (qg < NN && kg + e < NN) ? P[((size_t)bh * NN + qg) * NN + kg + e] : 0.f;
            __nv_bfloat162 hp0, lp0, hp1, lp1;
            split2(p[0], p[1], hp0, lp0); split2(p[2], p[3], hp1, lp1);
            uint32_t off = swz((q << 7) | (k4 << 1));
            *(__nv_bfloat162*)(smp + off)             = hp0;
            *(__nv_bfloat162*)(smp + off + 4)         = hp1;
            *(__nv_bfloat162*)(smp + 8192 + off)      = hp0;
            *(__nv_bfloat162*)(smp + 8192 + off + 4)  = hp1;
            *(__nv_bfloat162*)(smp + 16384 + off)     = lp0;
            *(__nv_bfloat162*)(smp + 16384 + off + 4) = lp1;
        }
        CP_WAIT0();
        __syncthreads();
        #pragma unroll
        for (int slab = 0; slab < 3; slab++) {
            #pragma unroll
            for (int ks = 0; ks < 4; ks++) {
                uint32_t afr[4];
                int arow = wid * 16 + ((a_mi & 1) << 3) + a_r;
                ldm_x4(afr, smP + slab * 8192 + swz((arow << 7) | ((ks * 2 + (a_mi >> 1)) << 4)));
                #pragma unroll
                for (int nfp = 0; nfp < 4; nfp++) {
                    uint32_t bfr[4];
                    int brow = (nfp * 2 + (b_grp >> 1)) * 8 + b_r;
                    ldm_x4(bfr, smV + slab * 8192 + swz((brow << 7) | ((ks * 2 + (b_grp & 1)) << 4)));
                    mma_bf16(acc[nfp * 2 + 0], afr, bfr);
                    mma_bf16(acc[nfp * 2 + 1], afr, bfr + 2);
                }
            }
        }
        __syncthreads();
    }
    int cr = lane >> 2, cc2 = (lane & 3) << 1;
    #pragma unroll
    for (int nf = 0; nf < 8; nf++) {
        #pragma unroll
        for (int half = 0; half < 2; half++) {
            int q = qt * 64 + wid * 16 + cr + half * 8;
            if (q < NN) {
                int m = b * NN + q;
                int col = h * HD + nf * 8 + cc2;
                __nv_bfloat162 hp, lp;
                split2(acc[nf][half * 2 + 0], acc[nf][half * 2 + 1], hp, lp);
                __nv_bfloat16* row = Ox3 + (size_t)m * (3 * CC);
                *(__nv_bfloat162*)(row + col) = hp;
                *(__nv_bfloat162*)(row + CC + col) = hp;
                *(__nv_bfloat162*)(row + 2 * CC + col) = lp;
            }
        }
    }
}

// ---------------- LayerNorm D=768 -> bf16x3 ----------------
__global__ void ln768_x3(const float* __restrict__ x, const float* __restrict__ g,
                         const float* __restrict__ b, __nv_bfloat16* __restrict__ out) {
    int row = blockIdx.x;
    const float* p = x + (size_t)row * CC;
    int tid = threadIdx.x;
    float v0 = p[tid], v1 = p[tid + 256], v2 = p[tid + 512];
    float s = v0 + v1 + v2;
    float sq = v0 * v0 + v1 * v1 + v2 * v2;
    __shared__ float rs[256], rq[256];
    rs[tid] = s; rq[tid] = sq; __syncthreads();
    for (int st = 128; st > 0; st >>= 1) {
        if (tid < st) { rs[tid] += rs[tid + st]; rq[tid] += rq[tid + st]; }
        __syncthreads();
    }
    float mean = rs[0] * (1.0f / CC);
    float var  = rq[0] * (1.0f / CC) - mean * mean;
    float inv = rsqrtf(var + 1e-5f);
    __nv_bfloat16* o = out + (size_t)row * (3 * CC);
    #pragma unroll
    for (int j = 0; j < 3; j++) {
        int c = tid + j * 256;
        float y = (p[c] - mean) * inv * g[c] + b[c];
        __nv_bfloat16 hi = __float2bfloat16(y);
        o[c] = hi; o[CC + c] = hi;
        o[2 * CC + c] = __float2bfloat16(y - __bfloat162float(hi));
    }
}

// ---------------- LayerNorm D=32 ----------------
__global__ void ln32_kernel(const float* __restrict__ x, const float* __restrict__ g,
                            const float* __restrict__ b, float* __restrict__ out) {
    int row = blockIdx.x * 8 + threadIdx.x / 32;
    int lane = threadIdx.x & 31;
    float v = x[(size_t)row * OUTC + lane];
    float s = v, sq = v * v;
    #pragma unroll
    for (int o = 16; o > 0; o >>= 1) {
        s  += __shfl_xor_sync(0xffffffff, s, o);
        sq += __shfl_xor_sync(0xffffffff, sq, o);
    }
    float mean = s * (1.0f / OUTC);
    float var  = sq * (1.0f / OUTC) - mean * mean;
    float inv = rsqrtf(var + 1e-5f);
    out[(size_t)row * OUTC + lane] = (v - mean) * inv * g[lane] + b[lane];
}

// ---------------- fp32 SIMT GEMM (small channel GEMMs) ----------------
template<int BM, int BN, int BK, int TM, int TN, bool GELU, bool RES>
__global__ void gemm_nt(const float* __restrict__ A, const float* __restrict__ Bw,
                        const float* __restrict__ bias, const float* __restrict__ res,
                        float* __restrict__ C, int M, int N, int K) {
    constexpr int THREADS = (BM / TM) * (BN / TN);
    __shared__ float As[BK][BM];
    __shared__ float Bs[BK][BN];
    int tid = threadIdx.x;
    int bm = blockIdx.y * BM, bn = blockIdx.x * BN;
    int tx = tid % (BN / TN), ty = tid / (BN / TN);
    float acc[TM][TN];
    #pragma unroll
    for (int i = 0; i < TM; i++)
        #pragma unroll
        for (int j = 0; j < TN; j++) acc[i][j] = 0.0f;
    constexpr int A4 = BM * BK / 4;
    constexpr int B4 = BN * BK / 4;
    for (int k0 = 0; k0 < K; k0 += BK) {
        #pragma unroll
        for (int i = tid; i < A4; i += THREADS) {
            int row = i / (BK / 4);
            int kk  = (i % (BK / 4)) * 4;
            float4 v = make_float4(0.f, 0.f, 0.f, 0.f);
            if (k0 + kk < K) v = *(const float4*)(A + (size_t)(bm + row) * K + k0 + kk);
            As[kk + 0][row] = v.x; As[kk + 1][row] = v.y;
            As[kk + 2][row] = v.z; As[kk + 3][row] = v.w;
        }
        #pragma unroll
        for (int i = tid; i < B4; i += THREADS) {
            int row = i / (BK / 4);
            int kk  = (i % (BK / 4)) * 4;
            float4 v = make_float4(0.f, 0.f, 0.f, 0.f);
            if (bn + row < N && k0 + kk < K)
                v = *(const float4*)(Bw + (size_t)(bn + row) * K + k0 + kk);
            Bs[kk + 0][row] = v.x; Bs[kk + 1][row] = v.y;
            Bs[kk + 2][row] = v.z; Bs[kk + 3][row] = v.w;
        }
        __syncthreads();
        #pragma unroll
        for (int kk = 0; kk < BK; kk++) {
            float a[TM], bv[TN];
            #pragma unroll
            for (int i = 0; i < TM; i++) a[i] = As[kk][ty * TM + i];
            #pragma unroll
            for (int j = 0; j < TN; j++) bv[j] = Bs[kk][tx * TN + j];
            #pragma unroll
            for (int i = 0; i < TM; i++)
                #pragma unroll
                for (int j = 0; j < TN; j++) acc[i][j] += a[i] * bv[j];
        }
        __syncthreads();
    }
    #pragma unroll
    for (int i = 0; i < TM; i++) {
        int gm = bm + ty * TM + i;
        #pragma unroll
        for (int j = 0; j < TN; j++) {
            int gn = bn + tx * TN + j;
            if (gn < N) {
                float v = acc[i][j];
                if (bias) v += bias[gn];
                if (GELU) v = gelu_f(v);
                if (RES) v += res[(size_t)gm * N + gn];
                C[(size_t)gm * N + gn] = v;
            }
        }
    }
}

// ---------------- warp-per-row softmax over 197 ----------------
__global__ void softmax197_warp(float* __restrict__ S) {
    int row = blockIdx.x * 8 + (threadIdx.x >> 5);
    int lane = threadIdx.x & 31;
    float* p = S + (size_t)row * NN;
    float v[7];
    float mx = -INFINITY;
    #pragma unroll
    for (int j = 0; j < 7; j++) {
        int idx = lane + 32 * j;
        v[j] = (idx < NN) ? p[idx] : -INFINITY;
        mx = fmaxf(mx, v[j]);
    }
    #pragma unroll
    for (int o = 16; o > 0; o >>= 1) mx = fmaxf(mx, __shfl_xor_sync(0xffffffff, mx, o));
    float sum = 0.0f;
    #pragma unroll
    for (int j = 0; j < 7; j++) { v[j] = __expf(v[j] - mx); sum += (lane + 32 * j < NN) ? v[j] : 0.0f; }
    #pragma unroll
    for (int o = 16; o > 0; o >>= 1) sum += __shfl_xor_sync(0xffffffff, sum, o);
    float inv = 1.0f / sum;
    #pragma unroll
    for (int j = 0; j < 7; j++) {
        int idx = lane + 32 * j;
        if (idx < NN) p[idx] = v[j] * inv;
    }
}

// ---------------- t[b,c,s] = ln3[b, 1+s, c] ----------------
__global__ void make_t_kernel(const float* __restrict__ ln3, float* __restrict__ t) {
    int idx = blockIdx.x * 256 + threadIdx.x;
    if (idx >= BB * OUTC * CNN) return;
    int s = idx % CNN;
    int c = (idx / CNN) % OUTC;
    int b = idx / (CNN * OUTC);
    t[idx] = ln3[((size_t)(b * NN + 1 + s)) * OUTC + c];
}

// ---------------- tiny channel attention ----------------
__global__ void chattn_kernel(const float* __restrict__ cqkv, float* __restrict__ co) {
    int b = blockIdx.x / CHH, h = blockIdx.x % CHH;
    int tid = threadIdx.x;
    __shared__ float Q[OUTC][CHD], Kk[OUTC][CHD], V[OUTC][CHD], S[OUTC][OUTC + 1];
    const float* base = cqkv + (size_t)b * OUTC * (3 * CNN);
    for (int i = tid; i < OUTC * CHD; i += 256) {
        int r = i / CHD, d = i % CHD;
        Q[r][d]  = base[r * (3 * CNN) + h * CHD + d];
        Kk[r][d] = base[r * (3 * CNN) + CNN + h * CHD + d];
        V[r][d]  = base[r * (3 * CNN) + 2 * CNN + h * CHD + d];
    }
    __syncthreads();
    const float sc = rsqrtf((float)CHD);
    for (int i = tid; i < OUTC * OUTC; i += 256) {
        int qi = i / OUTC, kj = i % OUTC;
        float s = 0.0f;
        #pragma unroll
        for (int d = 0; d < CHD; d++) s += Q[qi][d] * Kk[kj][d];
        S[qi][kj] = s * sc;
    }
    __syncthreads();
    if (tid < OUTC) {
        float mx = -INFINITY;
        #pragma unroll
        for (int j = 0; j < OUTC; j++) mx = fmaxf(mx, S[tid][j]);
        float sum = 0.0f;
        #pragma unroll
        for (int j = 0; j < OUTC; j++) { float e = __expf(S[tid][j] - mx); S[tid][j] = e; sum += e; }
        float inv = 1.0f / sum;
        #pragma unroll
        for (int j = 0; j < OUTC; j++) S[tid][j] *= inv;
    }
    __syncthreads();
    for (int i = tid; i < OUTC * CHD; i += 256) {
        int qi = i / CHD, d = i % CHD;
        float s = 0.0f;
        #pragma unroll
        for (int kk = 0; kk < OUTC; kk++) s += S[qi][kk] * V[kk][d];
        co[((size_t)(b * OUTC + qi)) * CNN + h * CHD + d] = s;
    }
}

// ---------------- x32 += concat([ln3 cls, co2^T]) ----------------
__global__ void concat_add_kernel(const float* __restrict__ ln3, const float* __restrict__ co2,
                                  float* __restrict__ x32) {
    int idx = blockIdx.x * 256 + threadIdx.x;
    if (idx >= MROWS * OUTC) return;
    int c = idx % OUTC;
    int n = (idx / OUTC) % NN;
    int b = idx / (OUTC * NN);
    float add;
    if (n == 0) add = ln3[((size_t)b * NN) * OUTC + c];
    else        add = co2[((size_t)(b * OUTC + c)) * CNN + (n - 1)];
    x32[idx] += add;
}

// ---------------- launch ----------------
static inline int cdiv(long long a, int b) { return (int)((a + b - 1) / b); }

extern "C" void kernel_launch(void* const* d_in, const int* in_sizes, int n_in,
                              void* d_out, int out_size) {
    const float* x      = (const float*)d_in[0];
    const float* g1     = (const float*)d_in[1];
    const float* b1     = (const float*)d_in[2];
    const float* w_qkv  = (const float*)d_in[3];
    const float* w_proj = (const float*)d_in[4];
    const float* b_proj = (const float*)d_in[5];
    const float* g2     = (const float*)d_in[6];
    const float* b2     = (const float*)d_in[7];
    const float* w_fc1  = (const float*)d_in[8];
    const float* b_fc1  = (const float*)d_in[9];
    const float* w_fc2  = (const float*)d_in[10];
    const float* b_fc2  = (const float*)d_in[11];
    const float* g3     = (const float*)d_in[12];
    const float* b3     = (const float*)d_in[13];
    const float* w_cqkv = (const float*)d_in[14];
    const float* w_cproj= (const float*)d_in[15];
    const float* b_cproj= (const float*)d_in[16];
    const float* g4     = (const float*)d_in[17];
    const float* b4     = (const float*)d_in[18];
    const float* w_cfc1 = (const float*)d_in[19];
    const float* b_cfc1 = (const float*)d_in[20];
    const float* w_cfc2 = (const float*)d_in[21];
    const float* b_cfc2 = (const float*)d_in[22];
    float* out = (float*)d_out;

    float *p_qkv, *p_attn, *p_x, *p_x32, *p_ln32, *p_t, *p_cqkv, *p_co, *p_co2, *p_cmlp;
    __nv_bfloat16 *p_abf, *p_abf2, *p_wbf, *p_qs, *p_ks, *p_vt;
    cudaGetSymbolAddress((void**)&p_qkv,  g_qkv);
    cudaGetSymbolAddress((void**)&p_attn, g_attn);
    cudaGetSymbolAddress((void**)&p_x,    g_x);
    cudaGetSymbolAddress((void**)&p_x32,  g_x32);
    cudaGetSymbolAddress((void**)&p_ln32, g_ln32);
    cudaGetSymbolAddress((void**)&p_t,    g_t);
    cudaGetSymbolAddress((void**)&p_cqkv, g_cqkv);
    cudaGetSymbolAddress((void**)&p_co,   g_co);
    cudaGetSymbolAddress((void**)&p_co2,  g_co2);
    cudaGetSymbolAddress((void**)&p_cmlp, g_cmlp);
    cudaGetSymbolAddress((void**)&p_abf,  g_abf);
    cudaGetSymbolAddress((void**)&p_abf2, g_abf2);
    cudaGetSymbolAddress((void**)&p_wbf,  g_wbf);
    cudaGetSymbolAddress((void**)&p_qs,   g_qs);
    cudaGetSymbolAddress((void**)&p_ks,   g_ks);
    cudaGetSymbolAddress((void**)&p_vt,   g_vt);

    const int SM128 = 3 * (128 * 128 + 128 * 128) + 1024;
    const int SM32  = 3 * (128 * 128 + 32 * 128) + 1024;
    cudaFuncSetAttribute(gemm_mma<128, false, false, false>, cudaFuncAttributeMaxDynamicSharedMemorySize, SM128);
    cudaFuncSetAttribute(gemm_mma<128, false, true,  false>, cudaFuncAttributeMaxDynamicSharedMemorySize, SM128);
    cudaFuncSetAttribute(gemm_mma<128, true,  false, true >, cudaFuncAttributeMaxDynamicSharedMemorySize, SM128);
    cudaFuncSetAttribute(gemm_mma<32,  false, false, false>, cudaFuncAttributeMaxDynamicSharedMemorySize, SM32);
    cudaFuncSetAttribute(gemm_mma<32,  false, true,  false>, cudaFuncAttributeMaxDynamicSharedMemorySize, SM32);

    const int M = MROWS;
    const int MB = M / 128;

    // 1. LN1 -> bf16x3
    ln768_x3<<<M, 256>>>(x, g1, b1, p_abf);
    // 2. qkv
    conv_wt<<<cdiv((long long)3 * CC * CC / 4, 256), 256>>>(w_qkv, p_wbf, 3 * CC, CC);
    gemm_mma<128, false, false, false><<<dim3(18, MB), 256, SM128>>>(p_abf, p_wbf, nullptr, nullptr, p_qkv, nullptr, M, 3 * CC, 3 * CC);
    // 3. attention (HMMA bf16x3)
    conv_qk<<<cdiv((long long)NBH * 197 * 32, 256), 256>>>(p_qkv, p_qs, p_ks);
    conv_vt<<<NBH * 4, 256>>>(p_qkv, p_vt);
    attn_qk_mma<<<dim3(4, 4, NBH), 128>>>(p_qs, p_ks, p_attn);
    softmax197_warp<<<NBH * NN / 8, 256>>>(p_attn);
    attn_av_mma<<<dim3(4, NBH), 128>>>(p_attn, p_vt, p_abf);
    // 4. x = x_in + O @ w_proj^T + b_proj
    conv_wt<<<cdiv((long long)CC * CC / 4, 256), 256>>>(w_proj, p_wbf, CC, CC);
    gemm_mma<128, false, true, false><<<dim3(6, MB), 256, SM128>>>(p_abf, p_wbf, b_proj, x, p_x, nullptr, M, CC, 3 * CC);
    // 5. LN2 -> bf16x3
    ln768_x3<<<M, 256>>>(p_x, g2, b2, p_abf);
    // 6. hidden = gelu(...) -> bf16x3 directly
    conv_wt<<<cdiv((long long)MLPH * CC / 4, 256), 256>>>(w_fc1, p_wbf, MLPH, CC);
    gemm_mma<128, true, false, true><<<dim3(24, MB), 256, SM128>>>(p_abf, p_wbf, b_fc1, nullptr, nullptr, p_abf2, M, MLPH, 3 * CC);
    // 7. x32 = hidden @ w_fc2^T + b_fc2
    conv_wt<<<cdiv((long long)OUTC * MLPH / 4, 256), 256>>>(w_fc2, p_wbf, OUTC, MLPH);
    gemm_mma<32, false, false, false><<<dim3(1, MB), 256, SM32>>>(p_abf2, p_wbf, b_fc2, nullptr, p_x32, nullptr, M, OUTC, 3 * MLPH);
    // 8. LN3
    ln32_kernel<<<M / 8, 256>>>(p_x32, g3, b3, p_ln32);
    // 9. channel branch
    make_t_kernel<<<(BB * OUTC * CNN + 255) / 256, 256>>>(p_ln32, p_t);
    gemm_nt<128, 128, 16, 8, 8, false, false><<<dim3(5, CMROWS / 128), 256>>>(p_t, w_cqkv, nullptr, nullptr, p_cqkv, CMROWS, 3 * CNN, CNN);
    chattn_kernel<<<BB * CHH, 256>>>(p_cqkv, p_co);
    gemm_nt<128, 128, 16, 8, 8, false, false><<<dim3(2, CMROWS / 128), 256>>>(p_co, w_cproj, b_cproj, nullptr, p_co2, CMROWS, CNN, CNN);
    concat_add_kernel<<<(M * OUTC + 255) / 256, 256>>>(p_ln32, p_co2, p_x32);
    // 10. LN4 + channel MLP
    ln32_kernel<<<M / 8, 256>>>(p_x32, g4, b4, p_ln32);
    gemm_nt<128, 128, 16, 8, 8, true, false><<<dim3(1, MB), 256>>>(p_ln32, w_cfc1, b_cfc1, nullptr, p_cmlp, M, CMLPH, OUTC);
    conv_act<<<cdiv((long long)M * CMLPH / 4, 256), 256>>>(p_cmlp, p_abf, M, CMLPH);
    conv_wt<<<cdiv((long long)OUTC * CMLPH / 4, 256), 256>>>(w_cfc2, p_wbf, OUTC, CMLPH);
    gemm_mma<32, false, true, false><<<dim3(1, MB), 256, SM32>>>(p_abf, p_wbf, b_cfc2, p_x32, out, nullptr, M, OUTC, 3 * CMLPH);
}

// round 7
// speedup vs baseline: 3.2718x; 1.0117x over previous
#include <cuda_runtime.h>
#include <cuda_bf16.h>
#include <math.h>
#include <stdint.h>
#include <stddef.h>

#define BB   128
#define NN   197
#define CC   768
#define HH   12
#define HD   64
#define OUTC 32
#define CHH  14
#define CHD  14
#define CNN  196
#define MLPH 3072
#define CMLPH 128
#define MROWS (BB*NN)          // 25216
#define CMROWS (BB*OUTC)       // 4096
#define NBH   (BB*HH)          // 1536

// ---------------- scratch ----------------
__device__ float g_qkv [MROWS*3*CC];
__device__ float g_attn[(size_t)NBH*NN*NN];
__device__ float g_x   [MROWS*CC];
__device__ float g_x32 [MROWS*OUTC];
__device__ float g_ln32[MROWS*OUTC];
__device__ float g_t   [BB*OUTC*CNN];
__device__ float g_cqkv[BB*OUTC*3*CNN];
__device__ float g_co  [BB*OUTC*CNN];
__device__ float g_co2 [BB*OUTC*CNN];
__device__ float g_cmlp[MROWS*CMLPH];
__device__ __nv_bfloat16 g_abf [(size_t)MROWS*3*CC];
__device__ __nv_bfloat16 g_abf2[(size_t)MROWS*3*MLPH];
__device__ __nv_bfloat16 g_wbf [(size_t)MLPH*3*CC];
__device__ __nv_bfloat16 g_qs  [(size_t)NBH*4*3*4096];
__device__ __nv_bfloat16 g_ks  [(size_t)NBH*4*3*4096];
__device__ __nv_bfloat16 g_vt  [(size_t)NBH*4*3*4096];

__device__ __forceinline__ float gelu_f(float x) {
    return 0.5f * x * (1.0f + erff(x * 0.70710678118654752440f));
}

// ================= PTX helpers =================
__device__ __forceinline__ uint32_t smem_u32(const void* p) {
    uint32_t a;
    asm("{ .reg .u64 t; cvta.to.shared.u64 t, %1; cvt.u32.u64 %0, t; }" : "=r"(a) : "l"(p));
    return a;
}
#define CP_ASYNC16(d, s)    asm volatile("cp.async.cg.shared.global [%0], [%1], 16;" :: "r"(d), "l"(s))
#define CP_COMMIT()         asm volatile("cp.async.commit_group;" ::: "memory")
#define CP_WAIT1()          asm volatile("cp.async.wait_group 1;" ::: "memory")
#define CP_WAIT2()          asm volatile("cp.async.wait_group 2;" ::: "memory")
#define CP_WAIT0()          asm volatile("cp.async.wait_group 0;" ::: "memory")

__device__ __forceinline__ void ldm_x4(uint32_t* r, uint32_t addr) {
    asm volatile("ldmatrix.sync.aligned.m8n8.x4.shared.b16 {%0,%1,%2,%3}, [%4];"
        : "=r"(r[0]), "=r"(r[1]), "=r"(r[2]), "=r"(r[3]) : "r"(addr));
}
__device__ __forceinline__ void mma_bf16(float* c, const uint32_t* a, const uint32_t* b) {
    asm volatile("mma.sync.aligned.m16n8k16.row.col.f32.bf16.bf16.f32 "
        "{%0,%1,%2,%3}, {%4,%5,%6,%7}, {%8,%9}, {%0,%1,%2,%3};"
        : "+f"(c[0]), "+f"(c[1]), "+f"(c[2]), "+f"(c[3])
        : "r"(a[0]), "r"(a[1]), "r"(a[2]), "r"(a[3]), "r"(b[0]), "r"(b[1]));
}
__device__ __forceinline__ uint32_t swz(uint32_t off) { return off ^ ((off >> 3) & 0x70); }
__device__ __forceinline__ void split2(float a, float b, __nv_bfloat162& hp, __nv_bfloat162& lp) {
    __nv_bfloat16 h0 = __float2bfloat16(a), h1 = __float2bfloat16(b);
    hp = __nv_bfloat162(h0, h1);
    lp = __nv_bfloat162(__float2bfloat16(a - __bfloat162float(h0)),
                        __float2bfloat16(b - __bfloat162float(h1)));
}

// ================= conversions =================
__global__ void conv_act(const float* __restrict__ in, __nv_bfloat16* __restrict__ out,
                         int Mr, int K) {
    long long idx = (long long)blockIdx.x * 256 + threadIdx.x;
    long long tot = (long long)Mr * (K / 4);
    if (idx >= tot) return;
    int m = (int)(idx / (K / 4)), k = (int)(idx % (K / 4)) * 4;
    float4 v = *(const float4*)(in + (size_t)m * K + k);
    __nv_bfloat162 hp0, lp0, hp1, lp1;
    split2(v.x, v.y, hp0, lp0); split2(v.z, v.w, hp1, lp1);
    __nv_bfloat16* row = out + (size_t)m * 3 * K;
    *(__nv_bfloat162*)(row + k) = hp0;           *(__nv_bfloat162*)(row + k + 2) = hp1;
    *(__nv_bfloat162*)(row + K + k) = hp0;       *(__nv_bfloat162*)(row + K + k + 2) = hp1;
    *(__nv_bfloat162*)(row + 2 * K + k) = lp0;   *(__nv_bfloat162*)(row + 2 * K + k + 2) = lp1;
}
__global__ void conv_wt(const float* __restrict__ in, __nv_bfloat16* __restrict__ out,
                        int Nr, int K) {
    long long idx = (long long)blockIdx.x * 256 + threadIdx.x;
    long long tot = (long long)Nr * (K / 4);
    if (idx >= tot) return;
    int n = (int)(idx / (K / 4)), k = (int)(idx % (K / 4)) * 4;
    float4 v = *(const float4*)(in + (size_t)n * K + k);
    __nv_bfloat162 hp0, lp0, hp1, lp1;
    split2(v.x, v.y, hp0, lp0); split2(v.z, v.w, hp1, lp1);
    __nv_bfloat16* row = out + (size_t)n * 3 * K;
    *(__nv_bfloat162*)(row + k) = hp0;           *(__nv_bfloat162*)(row + k + 2) = hp1;
    *(__nv_bfloat162*)(row + K + k) = lp0;       *(__nv_bfloat162*)(row + K + k + 2) = lp1;
    *(__nv_bfloat162*)(row + 2 * K + k) = hp0;   *(__nv_bfloat162*)(row + 2 * K + k + 2) = hp1;
}
__global__ void conv_qk(const float* __restrict__ qkv, __nv_bfloat16* __restrict__ Qs,
                        __nv_bfloat16* __restrict__ Ks) {
    int idx = blockIdx.x * 256 + threadIdx.x;
    if (idx >= NBH * 197 * 32) return;
    int d2 = (idx & 31) * 2;
    int n  = (idx >> 5) % 197;
    int bh = idx / (32 * 197);
    int b = bh / HH, h = bh % HH;
    const float* src = qkv + (size_t)(b * NN + n) * (3 * CC) + h * HD + d2;
    float2 q = *(const float2*)src;
    float2 k = *(const float2*)(src + CC);
    __nv_bfloat162 qh, ql, kh, kl;
    split2(q.x, q.y, qh, ql); split2(k.x, k.y, kh, kl);
    int qt = n >> 6, r = n & 63;
    size_t base = ((size_t)(bh * 4 + qt) * 3) * 4096 + r * 64 + d2;
    *(__nv_bfloat162*)(Qs + base)        = qh;
    *(__nv_bfloat162*)(Qs + base + 4096) = qh;
    *(__nv_bfloat162*)(Qs + base + 8192) = ql;
    *(__nv_bfloat162*)(Ks + base)        = kh;
    *(__nv_bfloat162*)(Ks + base + 4096) = kl;
    *(__nv_bfloat162*)(Ks + base + 8192) = kh;
}
__global__ void conv_vt(const float* __restrict__ qkv, __nv_bfloat16* __restrict__ Vt) {
    int ct = blockIdx.x;
    int bh = ct >> 2, kt = ct & 3;
    int b = bh / HH, h = bh % HH;
    __shared__ float t[64][65];
    int tid = threadIdx.x;
    for (int i = tid; i < 4096; i += 256) {
        int kk = i >> 6, d = i & 63;
        int k = kt * 64 + kk;
        t[kk][d] = (k < NN) ? qkv[(size_t)(b * NN + k) * (3 * CC) + 2 * CC + h * HD + d] : 0.f;
    }
    __syncthreads();
    __nv_bfloat16* dst = Vt + ((size_t)ct * 3) * 4096;
    for (int i = tid; i < 2048; i += 256) {
        int d = i >> 5, kk2 = (i & 31) << 1;
        __nv_bfloat162 hp, lp;
        split2(t[kk2][d], t[kk2 + 1][d], hp, lp);
        size_t base = (size_t)d * 64 + kk2;
        *(__nv_bfloat162*)(dst + base)        = hp;
        *(__nv_bfloat162*)(dst + base + 4096) = lp;
        *(__nv_bfloat162*)(dst + base + 8192) = hp;
    }
}

// ================= mma.sync bf16 NT GEMM (single-sync pipelined loop) =================
template<int BN, bool GELU, bool RES, bool X3>
__global__ void __launch_bounds__(256, 2)
gemm_mma(const __nv_bfloat16* __restrict__ A, const __nv_bfloat16* __restrict__ Bw,
         const float* __restrict__ bias, const float* __restrict__ res,
         float* __restrict__ C, __nv_bfloat16* __restrict__ Cx3, int M, int N, int Kp) {
    constexpr int A_BYTES = 128 * 128;
    constexpr int B_BYTES = BN * 128;
    constexpr int STAGE = A_BYTES + B_BYTES;
    constexpr int NSTG = 3;
    constexpr int WN = BN / 2;
    constexpr int MF = 2;
    constexpr int NF = WN / 8;

    extern __shared__ char smraw[];
    char* sm = (char*)(((uintptr_t)smraw + 1023) & ~(uintptr_t)1023);
    uint32_t smb = smem_u32(sm);

    int tid = threadIdx.x, wid = tid >> 5, lane = tid & 31;
    int wm = wid & 3, wn = wid >> 2;
    int bm = blockIdx.y * 128, bn = blockIdx.x * BN;
    const __nv_bfloat16* Ab = A + (size_t)bm * Kp;
    const __nv_bfloat16* Bb = Bw + (size_t)bn * Kp;
    const int nk = Kp >> 6;

    auto load_tile = [&](int kt, int s) {
        int k0 = kt << 6;
        uint32_t sa = smb + s * STAGE;
        #pragma unroll
        for (int i = 0; i < (128 * 8) / 256; i++) {
            int idx = tid + i * 256;
            int r = idx >> 3, cb = (idx & 7) << 4;
            CP_ASYNC16(sa + swz((r << 7) | cb), (const char*)(Ab + (size_t)r * Kp + k0) + cb);
        }
        uint32_t sb = sa + A_BYTES;
        #pragma unroll
        for (int i = 0; i < (BN * 8 + 255) / 256; i++) {
            int idx = tid + i * 256;
            if (BN * 8 % 256 == 0 || idx < BN * 8) {
                int r = idx >> 3, cb = (idx & 7) << 4;
                CP_ASYNC16(sb + swz((r << 7) | cb), (const char*)(Bb + (size_t)r * Kp + k0) + cb);
            }
        }
    };

    float acc[MF][NF][4];
    #pragma unroll
    for (int i = 0; i < MF; i++)
        #pragma unroll
        for (int j = 0; j < NF; j++)
            #pragma unroll
            for (int e = 0; e < 4; e++) acc[i][j][e] = 0.0f;

    load_tile(0, 0); CP_COMMIT();
    if (nk > 1) load_tile(1, 1);
    CP_COMMIT();

    int a_mi = lane >> 3, a_r = lane & 7;
    int b_grp = lane >> 3, b_r = lane & 7;

    for (int kt = 0; kt < nk; kt++) {
        CP_WAIT1();
        __syncthreads();
        // issue next load BEFORE compute; stage (kt+2)%3 was consumed at kt-1,
        // and the barrier above guarantees all warps finished iteration kt-1.
        if (kt + 2 < nk) load_tile(kt + 2, (kt + 2) % NSTG);
        CP_COMMIT();

        int s = kt % NSTG;
        uint32_t sa = smb + s * STAGE;
        uint32_t sb = sa + A_BYTES;
        #pragma unroll
        for (int ks = 0; ks < 4; ks++) {
            uint32_t afr[MF][4];
            #pragma unroll
            for (int mf = 0; mf < MF; mf++) {
                int row = wm * 32 + mf * 16 + ((a_mi & 1) << 3) + a_r;
                ldm_x4(afr[mf], sa + swz((row << 7) | ((ks * 2 + (a_mi >> 1)) << 4)));
            }
            #pragma unroll
            for (int nfp = 0; nfp < NF / 2; nfp++) {
                uint32_t bfr[4];
                int row = wn * WN + (nfp * 2 + (b_grp >> 1)) * 8 + b_r;
                ldm_x4(bfr, sb + swz((row << 7) | ((ks * 2 + (b_grp & 1)) << 4)));
                #pragma unroll
                for (int mf = 0; mf < MF; mf++) {
                    mma_bf16(acc[mf][nfp * 2 + 0], afr[mf], bfr);
                    mma_bf16(acc[mf][nfp * 2 + 1], afr[mf], bfr + 2);
                }
            }
        }
    }

    int cr = lane >> 2, cc2 = (lane & 3) << 1;
    #pragma unroll
    for (int mf = 0; mf < MF; mf++) {
        #pragma unroll
        for (int half = 0; half < 2; half++) {
            int gm = bm + wm * 32 + mf * 16 + cr + half * 8;
            #pragma unroll
            for (int nf = 0; nf < NF; nf++) {
                int gn = bn + wn * WN + nf * 8 + cc2;
                float v0 = acc[mf][nf][half * 2 + 0];
                float v1 = acc[mf][nf][half * 2 + 1];
                if (bias) { v0 += __ldg(&bias[gn]); v1 += __ldg(&bias[gn + 1]); }
                if (GELU) { v0 = gelu_f(v0); v1 = gelu_f(v1); }
                if (X3) {
                    __nv_bfloat162 hp, lp;
                    split2(v0, v1, hp, lp);
                    __nv_bfloat16* row = Cx3 + (size_t)gm * (3 * N);
                    *(__nv_bfloat162*)(row + gn) = hp;
                    *(__nv_bfloat162*)(row + N + gn) = hp;
                    *(__nv_bfloat162*)(row + 2 * N + gn) = lp;
                } else {
                    if (RES) {
                        float2 rv = *(const float2*)(res + (size_t)gm * N + gn);
                        v0 += rv.x; v1 += rv.y;
                    }
                    *(float2*)(C + (size_t)gm * N + gn) = make_float2(v0, v1);
                }
            }
        }
    }
}

// ================= HMMA attention =================
__global__ void __launch_bounds__(128)
attn_qk_mma(const __nv_bfloat16* __restrict__ Qs, const __nv_bfloat16* __restrict__ Ks,
            float* __restrict__ S) {
    __shared__ __align__(128) char sm[49152];
    char* smp = sm;
    uint32_t smb = smem_u32(sm);
    int kt = blockIdx.x, qt = blockIdx.y, bh = blockIdx.z;
    int tid = threadIdx.x, wid = tid >> 5, lane = tid & 31;
    const char* Qb = (const char*)(Qs + ((size_t)(bh * 4 + qt) * 3) * 4096);
    const char* Kb = (const char*)(Ks + ((size_t)(bh * 4 + kt) * 3) * 4096);
    for (int c = tid; c < 1536; c += 128) {
        int slab = c >> 9, rem = c & 511, row = rem >> 3, unit = rem & 7;
        uint32_t off = slab * 8192 + swz((row << 7) | (unit << 4));
        CP_ASYNC16(smb + off, Qb + (size_t)c * 16);
        CP_ASYNC16(smb + 24576 + off, Kb + (size_t)c * 16);
    }
    CP_COMMIT(); CP_WAIT0();
    __syncthreads();
    (void)smp;

    float acc[8][4];
    #pragma unroll
    for (int i = 0; i < 8; i++)
        #pragma unroll
        for (int e = 0; e < 4; e++) acc[i][e] = 0.f;
    int a_mi = lane >> 3, a_r = lane & 7, b_grp = lane >> 3, b_r = lane & 7;
    uint32_t smQ = smb, smK = smb + 24576;
    #pragma unroll
    for (int slab = 0; slab < 3; slab++) {
        #pragma unroll
        for (int ks = 0; ks < 4; ks++) {
            uint32_t afr[4];
            int arow = wid * 16 + ((a_mi & 1) << 3) + a_r;
            ldm_x4(afr, smQ + slab * 8192 + swz((arow << 7) | ((ks * 2 + (a_mi >> 1)) << 4)));
            #pragma unroll
            for (int nfp = 0; nfp < 4; nfp++) {
                uint32_t bfr[4];
                int brow = (nfp * 2 + (b_grp >> 1)) * 8 + b_r;
                ldm_x4(bfr, smK + slab * 8192 + swz((brow << 7) | ((ks * 2 + (b_grp & 1)) << 4)));
                mma_bf16(acc[nfp * 2 + 0], afr, bfr);
                mma_bf16(acc[nfp * 2 + 1], afr, bfr + 2);
            }
        }
    }
    int cr = lane >> 2, cc2 = (lane & 3) << 1;
    #pragma unroll
    for (int nf = 0; nf < 8; nf++) {
        #pragma unroll
        for (int half = 0; half < 2; half++) {
            int q = qt * 64 + wid * 16 + cr + half * 8;
            int k = kt * 64 + nf * 8 + cc2;
            if (q < NN) {
                float* dst = S + ((size_t)bh * NN + q) * NN + k;
                if (k < NN)     dst[0] = acc[nf][half * 2 + 0] * 0.125f;
                if (k + 1 < NN) dst[1] = acc[nf][half * 2 + 1] * 0.125f;
            }
        }
    }
}

__global__ void __launch_bounds__(128)
attn_av_mma(const float* __restrict__ P, const __nv_bfloat16* __restrict__ Vt,
            __nv_bfloat16* __restrict__ Ox3) {
    __shared__ __align__(128) char sm[49152];
    char* smp = sm;
    uint32_t smb = smem_u32(sm);
    int qt = blockIdx.x, bh = blockIdx.y;
    int b = bh / HH, h = bh % HH;
    int tid = threadIdx.x, wid = tid >> 5, lane = tid & 31;
    float acc[8][4];
    #pragma unroll
    for (int i = 0; i < 8; i++)
        #pragma unroll
        for (int e = 0; e < 4; e++) acc[i][e] = 0.f;
    int a_mi = lane >> 3, a_r = lane & 7, b_grp = lane >> 3, b_r = lane & 7;
    uint32_t smP = smb, smV = smb + 24576;

    for (int kt = 0; kt < 4; kt++) {
        const char* Vb = (const char*)(Vt + ((size_t)(bh * 4 + kt) * 3) * 4096);
        for (int c = tid; c < 1536; c += 128) {
            int slab = c >> 9, rem = c & 511, row = rem >> 3, unit = rem & 7;
            CP_ASYNC16(smV + slab * 8192 + swz((row << 7) | (unit << 4)), Vb + (size_t)c * 16);
        }
        CP_COMMIT();
        #pragma unroll
        for (int i = 0; i < 8; i++) {
            int lin = i * 128 + tid;
            int q = lin >> 4, k4 = (lin & 15) << 2;
            int qg = qt * 64 + q, kg = kt * 64 + k4;
            float p[4];
            #pragma unroll
            for (int e = 0; e < 4; e++)
                p[e] = (qg < NN && kg + e < NN) ? P[((size_t)bh * NN + qg) * NN + kg + e] : 0.f;
            __nv_bfloat162 hp0, lp0, hp1, lp1;
            split2(p[0], p[1], hp0, lp0); split2(p[2], p[3], hp1, lp1);
            uint32_t off = swz((q << 7) | (k4 << 1));
            *(__nv_bfloat162*)(smp + off)             = hp0;
            *(__nv_bfloat162*)(smp + off + 4)         = hp1;
            *(__nv_bfloat162*)(smp + 8192 + off)      = hp0;
            *(__nv_bfloat162*)(smp + 8192 + off + 4)  = hp1;
            *(__nv_bfloat162*)(smp + 16384 + off)     = lp0;
            *(__nv_bfloat162*)(smp + 16384 + off + 4) = lp1;
        }
        CP_WAIT0();
        __syncthreads();
        #pragma unroll
        for (int slab = 0; slab < 3; slab++) {
            #pragma unroll
            for (int ks = 0; ks < 4; ks++) {
                uint32_t afr[4];
                int arow = wid * 16 + ((a_mi & 1) << 3) + a_r;
                ldm_x4(afr, smP + slab * 8192 + swz((arow << 7) | ((ks * 2 + (a_mi >> 1)) << 4)));
                #pragma unroll
                for (int nfp = 0; nfp < 4; nfp++) {
                    uint32_t bfr[4];
                    int brow = (nfp * 2 + (b_grp >> 1)) * 8 + b_r;
                    ldm_x4(bfr, smV + slab * 8192 + swz((brow << 7) | ((ks * 2 + (b_grp & 1)) << 4)));
                    mma_bf16(acc[nfp * 2 + 0], afr, bfr);
                    mma_bf16(acc[nfp * 2 + 1], afr, bfr + 2);
                }
            }
        }
        __syncthreads();
    }
    int cr = lane >> 2, cc2 = (lane & 3) << 1;
    #pragma unroll
    for (int nf = 0; nf < 8; nf++) {
        #pragma unroll
        for (int half = 0; half < 2; half++) {
            int q = qt * 64 + wid * 16 + cr + half * 8;
            if (q < NN) {
                int m = b * NN + q;
                int col = h * HD + nf * 8 + cc2;
                __nv_bfloat162 hp, lp;
                split2(acc[nf][half * 2 + 0], acc[nf][half * 2 + 1], hp, lp);
                __nv_bfloat16* row = Ox3 + (size_t)m * (3 * CC);
                *(__nv_bfloat162*)(row + col) = hp;
                *(__nv_bfloat162*)(row + CC + col) = hp;
                *(__nv_bfloat162*)(row + 2 * CC + col) = lp;
            }
        }
    }
}

// ---------------- LayerNorm D=768 -> bf16x3 ----------------
__global__ void ln768_x3(const float* __restrict__ x, const float* __restrict__ g,
                         const float* __restrict__ b, __nv_bfloat16* __restrict__ out) {
    int row = blockIdx.x;
    const float* p = x + (size_t)row * CC;
    int tid = threadIdx.x;
    float v0 = p[tid], v1 = p[tid + 256], v2 = p[tid + 512];
    float s = v0 + v1 + v2;
    float sq = v0 * v0 + v1 * v1 + v2 * v2;
    __shared__ float rs[256], rq[256];
    rs[tid] = s; rq[tid] = sq; __syncthreads();
    for (int st = 128; st > 0; st >>= 1) {
        if (tid < st) { rs[tid] += rs[tid + st]; rq[tid] += rq[tid + st]; }
        __syncthreads();
    }
    float mean = rs[0] * (1.0f / CC);
    float var  = rq[0] * (1.0f / CC) - mean * mean;
    float inv = rsqrtf(var + 1e-5f);
    __nv_bfloat16* o = out + (size_t)row * (3 * CC);
    #pragma unroll
    for (int j = 0; j < 3; j++) {
        int c = tid + j * 256;
        float y = (p[c] - mean) * inv * g[c] + b[c];
        __nv_bfloat16 hi = __float2bfloat16(y);
        o[c] = hi; o[CC + c] = hi;
        o[2 * CC + c] = __float2bfloat16(y - __bfloat162float(hi));
    }
}

// ---------------- LayerNorm D=32 ----------------
__global__ void ln32_kernel(const float* __restrict__ x, const float* __restrict__ g,
                            const float* __restrict__ b, float* __restrict__ out) {
    int row = blockIdx.x * 8 + threadIdx.x / 32;
    int lane = threadIdx.x & 31;
    float v = x[(size_t)row * OUTC + lane];
    float s = v, sq = v * v;
    #pragma unroll
    for (int o = 16; o > 0; o >>= 1) {
        s  += __shfl_xor_sync(0xffffffff, s, o);
        sq += __shfl_xor_sync(0xffffffff, sq, o);
    }
    float mean = s * (1.0f / OUTC);
    float var  = sq * (1.0f / OUTC) - mean * mean;
    float inv = rsqrtf(var + 1e-5f);
    out[(size_t)row * OUTC + lane] = (v - mean) * inv * g[lane] + b[lane];
}

// ---------------- fp32 SIMT GEMM (small channel GEMMs) ----------------
template<int BM, int BN, int BK, int TM, int TN, bool GELU, bool RES>
__global__ void gemm_nt(const float* __restrict__ A, const float* __restrict__ Bw,
                        const float* __restrict__ bias, const float* __restrict__ res,
                        float* __restrict__ C, int M, int N, int K) {
    constexpr int THREADS = (BM / TM) * (BN / TN);
    __shared__ float As[BK][BM];
    __shared__ float Bs[BK][BN];
    int tid = threadIdx.x;
    int bm = blockIdx.y * BM, bn = blockIdx.x * BN;
    int tx = tid % (BN / TN), ty = tid / (BN / TN);
    float acc[TM][TN];
    #pragma unroll
    for (int i = 0; i < TM; i++)
        #pragma unroll
        for (int j = 0; j < TN; j++) acc[i][j] = 0.0f;
    constexpr int A4 = BM * BK / 4;
    constexpr int B4 = BN * BK / 4;
    for (int k0 = 0; k0 < K; k0 += BK) {
        #pragma unroll
        for (int i = tid; i < A4; i += THREADS) {
            int row = i / (BK / 4);
            int kk  = (i % (BK / 4)) * 4;
            float4 v = make_float4(0.f, 0.f, 0.f, 0.f);
            if (k0 + kk < K) v = *(const float4*)(A + (size_t)(bm + row) * K + k0 + kk);
            As[kk + 0][row] = v.x; As[kk + 1][row] = v.y;
            As[kk + 2][row] = v.z; As[kk + 3][row] = v.w;
        }
        #pragma unroll
        for (int i = tid; i < B4; i += THREADS) {
            int row = i / (BK / 4);
            int kk  = (i % (BK / 4)) * 4;
            float4 v = make_float4(0.f, 0.f, 0.f, 0.f);
            if (bn + row < N && k0 + kk < K)
                v = *(const float4*)(Bw + (size_t)(bn + row) * K + k0 + kk);
            Bs[kk + 0][row] = v.x; Bs[kk + 1][row] = v.y;
            Bs[kk + 2][row] = v.z; Bs[kk + 3][row] = v.w;
        }
        __syncthreads();
        #pragma unroll
        for (int kk = 0; kk < BK; kk++) {
            float a[TM], bv[TN];
            #pragma unroll
            for (int i = 0; i < TM; i++) a[i] = As[kk][ty * TM + i];
            #pragma unroll
            for (int j = 0; j < TN; j++) bv[j] = Bs[kk][tx * TN + j];
            #pragma unroll
            for (int i = 0; i < TM; i++)
                #pragma unroll
                for (int j = 0; j < TN; j++) acc[i][j] += a[i] * bv[j];
        }
        __syncthreads();
    }
    #pragma unroll
    for (int i = 0; i < TM; i++) {
        int gm = bm + ty * TM + i;
        #pragma unroll
        for (int j = 0; j < TN; j++) {
            int gn = bn + tx * TN + j;
            if (gn < N) {
                float v = acc[i][j];
                if (bias) v += bias[gn];
                if (GELU) v = gelu_f(v);
                if (RES) v += res[(size_t)gm * N + gn];
                C[(size_t)gm * N + gn] = v;
            }
        }
    }
}

// ---------------- warp-per-row softmax over 197 ----------------
__global__ void softmax197_warp(float* __restrict__ S) {
    int row = blockIdx.x * 8 + (threadIdx.x >> 5);
    int lane = threadIdx.x & 31;
    float* p = S + (size_t)row * NN;
    float v[7];
    float mx = -INFINITY;
    #pragma unroll
    for (int j = 0; j < 7; j++) {
        int idx = lane + 32 * j;
        v[j] = (idx < NN) ? p[idx] : -INFINITY;
        mx = fmaxf(mx, v[j]);
    }
    #pragma unroll
    for (int o = 16; o > 0; o >>= 1) mx = fmaxf(mx, __shfl_xor_sync(0xffffffff, mx, o));
    float sum = 0.0f;
    #pragma unroll
    for (int j = 0; j < 7; j++) { v[j] = __expf(v[j] - mx); sum += (lane + 32 * j < NN) ? v[j] : 0.0f; }
    #pragma unroll
    for (int o = 16; o > 0; o >>= 1) sum += __shfl_xor_sync(0xffffffff, sum, o);
    float inv = 1.0f / sum;
    #pragma unroll
    for (int j = 0; j < 7; j++) {
        int idx = lane + 32 * j;
        if (idx < NN) p[idx] = v[j] * inv;
    }
}

// ---------------- t[b,c,s] = ln3[b, 1+s, c] ----------------
__global__ void make_t_kernel(const float* __restrict__ ln3, float* __restrict__ t) {
    int idx = blockIdx.x * 256 + threadIdx.x;
    if (idx >= BB * OUTC * CNN) return;
    int s = idx % CNN;
    int c = (idx / CNN) % OUTC;
    int b = idx / (CNN * OUTC);
    t[idx] = ln3[((size_t)(b * NN + 1 + s)) * OUTC + c];
}

// ---------------- tiny channel attention ----------------
__global__ void chattn_kernel(const float* __restrict__ cqkv, float* __restrict__ co) {
    int b = blockIdx.x / CHH, h = blockIdx.x % CHH;
    int tid = threadIdx.x;
    __shared__ float Q[OUTC][CHD], Kk[OUTC][CHD], V[OUTC][CHD], S[OUTC][OUTC + 1];
    const float* base = cqkv + (size_t)b * OUTC * (3 * CNN);
    for (int i = tid; i < OUTC * CHD; i += 256) {
        int r = i / CHD, d = i % CHD;
        Q[r][d]  = base[r * (3 * CNN) + h * CHD + d];
        Kk[r][d] = base[r * (3 * CNN) + CNN + h * CHD + d];
        V[r][d]  = base[r * (3 * CNN) + 2 * CNN + h * CHD + d];
    }
    __syncthreads();
    const float sc = rsqrtf((float)CHD);
    for (int i = tid; i < OUTC * OUTC; i += 256) {
        int qi = i / OUTC, kj = i % OUTC;
        float s = 0.0f;
        #pragma unroll
        for (int d = 0; d < CHD; d++) s += Q[qi][d] * Kk[kj][d];
        S[qi][kj] = s * sc;
    }
    __syncthreads();
    if (tid < OUTC) {
        float mx = -INFINITY;
        #pragma unroll
        for (int j = 0; j < OUTC; j++) mx = fmaxf(mx, S[tid][j]);
        float sum = 0.0f;
        #pragma unroll
        for (int j = 0; j < OUTC; j++) { float e = __expf(S[tid][j] - mx); S[tid][j] = e; sum += e; }
        float inv = 1.0f / sum;
        #pragma unroll
        for (int j = 0; j < OUTC; j++) S[tid][j] *= inv;
    }
    __syncthreads();
    for (int i = tid; i < OUTC * CHD; i += 256) {
        int qi = i / CHD, d = i % CHD;
        float s = 0.0f;
        #pragma unroll
        for (int kk = 0; kk < OUTC; kk++) s += S[qi][kk] * V[kk][d];
        co[((size_t)(b * OUTC + qi)) * CNN + h * CHD + d] = s;
    }
}

// ---------------- x32 += concat([ln3 cls, co2^T]) ----------------
__global__ void concat_add_kernel(const float* __restrict__ ln3, const float* __restrict__ co2,
                                  float* __restrict__ x32) {
    int idx = blockIdx.x * 256 + threadIdx.x;
    if (idx >= MROWS * OUTC) return;
    int c = idx % OUTC;
    int n = (idx / OUTC) % NN;
    int b = idx / (OUTC * NN);
    float add;
    if (n == 0) add = ln3[((size_t)b * NN) * OUTC + c];
    else        add = co2[((size_t)(b * OUTC + c)) * CNN + (n - 1)];
    x32[idx] += add;
}

// ---------------- launch ----------------
static inline int cdiv(long long a, int b) { return (int)((a + b - 1) / b); }

extern "C" void kernel_launch(void* const* d_in, const int* in_sizes, int n_in,
                              void* d_out, int out_size) {
    const float* x      = (const float*)d_in[0];
    const float* g1     = (const float*)d_in[1];
    const float* b1     = (const float*)d_in[2];
    const float* w_qkv  = (const float*)d_in[3];
    const float* w_proj = (const float*)d_in[4];
    const float* b_proj = (const float*)d_in[5];
    const float* g2     = (const float*)d_in[6];
    const float* b2     = (const float*)d_in[7];
    const float* w_fc1  = (const float*)d_in[8];
    const float* b_fc1  = (const float*)d_in[9];
    const float* w_fc2  = (const float*)d_in[10];
    const float* b_fc2  = (const float*)d_in[11];
    const float* g3     = (const float*)d_in[12];
    const float* b3     = (const float*)d_in[13];
    const float* w_cqkv = (const float*)d_in[14];
    const float* w_cproj= (const float*)d_in[15];
    const float* b_cproj= (const float*)d_in[16];
    const float* g4     = (const float*)d_in[17];
    const float* b4     = (const float*)d_in[18];
    const float* w_cfc1 = (const float*)d_in[19];
    const float* b_cfc1 = (const float*)d_in[20];
    const float* w_cfc2 = (const float*)d_in[21];
    const float* b_cfc2 = (const float*)d_in[22];
    float* out = (float*)d_out;

    float *p_qkv, *p_attn, *p_x, *p_x32, *p_ln32, *p_t, *p_cqkv, *p_co, *p_co2, *p_cmlp;
    __nv_bfloat16 *p_abf, *p_abf2, *p_wbf, *p_qs, *p_ks, *p_vt;
    cudaGetSymbolAddress((void**)&p_qkv,  g_qkv);
    cudaGetSymbolAddress((void**)&p_attn, g_attn);
    cudaGetSymbolAddress((void**)&p_x,    g_x);
    cudaGetSymbolAddress((void**)&p_x32,  g_x32);
    cudaGetSymbolAddress((void**)&p_ln32, g_ln32);
    cudaGetSymbolAddress((void**)&p_t,    g_t);
    cudaGetSymbolAddress((void**)&p_cqkv, g_cqkv);
    cudaGetSymbolAddress((void**)&p_co,   g_co);
    cudaGetSymbolAddress((void**)&p_co2,  g_co2);
    cudaGetSymbolAddress((void**)&p_cmlp, g_cmlp);
    cudaGetSymbolAddress((void**)&p_abf,  g_abf);
    cudaGetSymbolAddress((void**)&p_abf2, g_abf2);
    cudaGetSymbolAddress((void**)&p_wbf,  g_wbf);
    cudaGetSymbolAddress((void**)&p_qs,   g_qs);
    cudaGetSymbolAddress((void**)&p_ks,   g_ks);
    cudaGetSymbolAddress((void**)&p_vt,   g_vt);

    const int SM128 = 3 * (128 * 128 + 128 * 128) + 1024;
    const int SM32  = 3 * (128 * 128 + 32 * 128) + 1024;
    cudaFuncSetAttribute(gemm_mma<128, false, false, false>, cudaFuncAttributeMaxDynamicSharedMemorySize, SM128);
    cudaFuncSetAttribute(gemm_mma<128, false, true,  false>, cudaFuncAttributeMaxDynamicSharedMemorySize, SM128);
    cudaFuncSetAttribute(gemm_mma<128, true,  false, true >, cudaFuncAttributeMaxDynamicSharedMemorySize, SM128);
    cudaFuncSetAttribute(gemm_mma<32,  false, false, false>, cudaFuncAttributeMaxDynamicSharedMemorySize, SM32);
    cudaFuncSetAttribute(gemm_mma<32,  false, true,  false>, cudaFuncAttributeMaxDynamicSharedMemorySize, SM32);

    const int M = MROWS;
    const int MB = M / 128;

    // 1. LN1 -> bf16x3
    ln768_x3<<<M, 256>>>(x, g1, b1, p_abf);
    // 2. qkv
    conv_wt<<<cdiv((long long)3 * CC * CC / 4, 256), 256>>>(w_qkv, p_wbf, 3 * CC, CC);
    gemm_mma<128, false, false, false><<<dim3(18, MB), 256, SM128>>>(p_abf, p_wbf, nullptr, nullptr, p_qkv, nullptr, M, 3 * CC, 3 * CC);
    // 3. attention (HMMA bf16x3)
    conv_qk<<<cdiv((long long)NBH * 197 * 32, 256), 256>>>(p_qkv, p_qs, p_ks);
    conv_vt<<<NBH * 4, 256>>>(p_qkv, p_vt);
    attn_qk_mma<<<dim3(4, 4, NBH), 128>>>(p_qs, p_ks, p_attn);
    softmax197_warp<<<NBH * NN / 8, 256>>>(p_attn);
    attn_av_mma<<<dim3(4, NBH), 128>>>(p_attn, p_vt, p_abf);
    // 4. x = x_in + O @ w_proj^T + b_proj
    conv_wt<<<cdiv((long long)CC * CC / 4, 256), 256>>>(w_proj, p_wbf, CC, CC);
    gemm_mma<128, false, true, false><<<dim3(6, MB), 256, SM128>>>(p_abf, p_wbf, b_proj, x, p_x, nullptr, M, CC, 3 * CC);
    // 5. LN2 -> bf16x3
    ln768_x3<<<M, 256>>>(p_x, g2, b2, p_abf);
    // 6. hidden = gelu(...) -> bf16x3 directly
    conv_wt<<<cdiv((long long)MLPH * CC / 4, 256), 256>>>(w_fc1, p_wbf, MLPH, CC);
    gemm_mma<128, true, false, true><<<dim3(24, MB), 256, SM128>>>(p_abf, p_wbf, b_fc1, nullptr, nullptr, p_abf2, M, MLPH, 3 * CC);
    // 7. x32 = hidden @ w_fc2^T + b_fc2
    conv_wt<<<cdiv((long long)OUTC * MLPH / 4, 256), 256>>>(w_fc2, p_wbf, OUTC, MLPH);
    gemm_mma<32, false, false, false><<<dim3(1, MB), 256, SM32>>>(p_abf2, p_wbf, b_fc2, nullptr, p_x32, nullptr, M, OUTC, 3 * MLPH);
    // 8. LN3
    ln32_kernel<<<M / 8, 256>>>(p_x32, g3, b3, p_ln32);
    // 9. channel branch
    make_t_kernel<<<(BB * OUTC * CNN + 255) / 256, 256>>>(p_ln32, p_t);
    gemm_nt<128, 128, 16, 8, 8, false, false><<<dim3(5, CMROWS / 128), 256>>>(p_t, w_cqkv, nullptr, nullptr, p_cqkv, CMROWS, 3 * CNN, CNN);
    chattn_kernel<<<BB * CHH, 256>>>(p_cqkv, p_co);
    gemm_nt<128, 128, 16, 8, 8, false, false><<<dim3(2, CMROWS / 128), 256>>>(p_co, w_cproj, b_cproj, nullptr, p_co2, CMROWS, CNN, CNN);
    concat_add_kernel<<<(M * OUTC + 255) / 256, 256>>>(p_ln32, p_co2, p_x32);
    // 10. LN4 + channel MLP
    ln32_kernel<<<M / 8, 256>>>(p_x32, g4, b4, p_ln32);
    gemm_nt<128, 128, 16, 8, 8, true, false><<<dim3(1, MB), 256>>>(p_ln32, w_cfc1, b_cfc1, nullptr, p_cmlp, M, CMLPH, OUTC);
    conv_act<<<cdiv((long long)M * CMLPH / 4, 256), 256>>>(p_cmlp, p_abf, M, CMLPH);
    conv_wt<<<cdiv((long long)OUTC * CMLPH / 4, 256), 256>>>(w_cfc2, p_wbf, OUTC, CMLPH);
    gemm_mma<32, false, true, false><<<dim3(1, MB), 256, SM32>>>(p_abf, p_wbf, b_cfc2, p_x32, out, nullptr, M, OUTC, 3 * CMLPH);
}